// round 14
// baseline (speedup 1.0000x reference)
#include <cuda_runtime.h>
#include <cuda_bf16.h>
#include <cuda_fp16.h>
#include <math.h>
#include <stdint.h>

// Problem constants
#define B_   32
#define TQ   256
#define TK   1024
#define D_   512
#define NH   4
#define PROJ 512
#define HP   (NH * PROJ)      // 2048
#define HD   (NH * D_)        // 2048
#define A_ELEMS (4LL * 32 * 256 * 1024)   // 33554432

typedef long long ll;

// ---------------------------------------------------------------------------
// Scratch (static device arrays — sanctioned workaround for no-alloc rule)
// ---------------------------------------------------------------------------
__device__ __align__(128) __nv_bfloat16 g_s_hi[(size_t)B_ * TQ * D_];
__device__ __align__(128) __nv_bfloat16 g_s_lo[(size_t)B_ * TQ * D_];
__device__ __align__(128) __nv_bfloat16 g_h_hi[(size_t)B_ * TK * D_];
__device__ __align__(128) __nv_bfloat16 g_h_lo[(size_t)B_ * TK * D_];
__device__ __align__(128) __half        g_ht_f16[(size_t)B_ * D_ * TK];
__device__ __align__(128) __nv_bfloat16 g_ms_hi[(size_t)B_ * TQ * HP];   // sG
__device__ __align__(128) __nv_bfloat16 g_ms_lo[(size_t)B_ * TQ * HP];
__device__ __align__(128) __half        g_a_f16[(size_t)A_ELEMS];
__device__ __align__(128) __half        g_ctx_f16[(size_t)B_ * TQ * HD];
__device__ __align__(128) __half        g_Wred_f16[(size_t)D_ * HD];
// G-decomposition scratch
__device__ __align__(128) float         g_Wphi_f[(size_t)HP * D_];
__device__ __align__(128) float         g_Wpsi_f[(size_t)PROJ * D_];
__device__ __align__(128) __nv_bfloat16 g_WphiT_hi[(size_t)D_ * HP];
__device__ __align__(128) __nv_bfloat16 g_WphiT_lo[(size_t)D_ * HP];
__device__ __align__(128) __nv_bfloat16 g_WpsiT_hi[(size_t)D_ * PROJ];
__device__ __align__(128) __nv_bfloat16 g_WpsiT_lo[(size_t)D_ * PROJ];
__device__ __align__(128) __nv_bfloat16 g_Gt_hi[(size_t)NH * D_ * D_];
__device__ __align__(128) __nv_bfloat16 g_Gt_lo[(size_t)NH * D_ * D_];
__device__ __align__(128) float         g_u[(size_t)NH * D_];
__device__ __align__(128) float         g_cb[(size_t)NH * B_ * TK];
__device__ float g_bphi[HP];
__device__ float g_bred[D_];

// ---------------------------------------------------------------------------
// Helpers
// ---------------------------------------------------------------------------
__device__ __forceinline__ uint32_t smem_to_u32(const void* p) {
    uint32_t a;
    asm("{ .reg .u64 t; cvta.to.shared.u64 t, %1; cvt.u32.u64 %0, t; }"
        : "=r"(a) : "l"(p));
    return a;
}

__device__ __forceinline__ void ldsm4(uint32_t addr, uint32_t& r0, uint32_t& r1,
                                      uint32_t& r2, uint32_t& r3)
{
    asm volatile("ldmatrix.sync.aligned.m8n8.x4.shared.b16 {%0,%1,%2,%3}, [%4];"
                 : "=r"(r0), "=r"(r1), "=r"(r2), "=r"(r3) : "r"(addr));
}

__device__ __forceinline__ void hmma_bf16(float* c, uint32_t a0, uint32_t a1,
                                          uint32_t a2, uint32_t a3,
                                          uint32_t b0, uint32_t b1)
{
    asm volatile(
        "mma.sync.aligned.m16n8k16.row.col.f32.bf16.bf16.f32 "
        "{%0,%1,%2,%3}, {%4,%5,%6,%7}, {%8,%9}, {%0,%1,%2,%3};"
        : "+f"(c[0]), "+f"(c[1]), "+f"(c[2]), "+f"(c[3])
        : "r"(a0), "r"(a1), "r"(a2), "r"(a3), "r"(b0), "r"(b1));
}

__device__ __forceinline__ void hmma_fp16(float* c, uint32_t a0, uint32_t a1,
                                          uint32_t a2, uint32_t a3,
                                          uint32_t b0, uint32_t b1)
{
    asm volatile(
        "mma.sync.aligned.m16n8k16.row.col.f32.f16.f16.f32 "
        "{%0,%1,%2,%3}, {%4,%5,%6,%7}, {%8,%9}, {%0,%1,%2,%3};"
        : "+f"(c[0]), "+f"(c[1]), "+f"(c[2]), "+f"(c[3])
        : "r"(a0), "r"(a1), "r"(a2), "r"(a3), "r"(b0), "r"(b1));
}

#define CP_ASYNC16(sa, ga) \
    asm volatile("cp.async.cg.shared.global [%0], [%1], 16;" :: "r"(sa), "l"(ga))
#define CP_COMMIT() asm volatile("cp.async.commit_group;" ::: "memory")
#define CP_WAIT1()  asm volatile("cp.async.wait_group 1;" ::: "memory")
#define CP_WAIT0()  asm volatile("cp.async.wait_group 0;" ::: "memory")

// ---------------------------------------------------------------------------
// smem: 3-stage ring.
// MODE 0 (3-pass bf16 pairs): 3 stages x {Ahi,Alo,Bhi,Blo} = 192 KB
// MODE 1 (1-pass fp16):       3 stages x {A,B} = 96 KB
// ---------------------------------------------------------------------------
#define TILE_SZ 16384
#define EP_PITCH 132
#define SMEM_MODE0 (12 * TILE_SZ)          // 196608
#define SMEM_MODE1 (6 * TILE_SZ)           // 98304 (>= 67584 epilogue pad)

// Load one 128x64 bf16/fp16 tile (rows row0.., cols k0..k0+63) into swizzled smem.
__device__ __forceinline__ void tile_cp(const __nv_bfloat16* __restrict__ g,
                                        ll stride, ll row0, ll k0,
                                        uint32_t stile, int tid)
{
    int c = tid & 7;           // 16B chunk within row
    int r0 = tid >> 3;         // 0..31
    const char* gp = (const char*)(g + row0 * stride + k0 + c * 8);
    ll rb = stride * 2;
#pragma unroll
    for (int i = 0; i < 4; i++) {
        int r = r0 + i * 32;
        uint32_t sa = stile + (uint32_t)(r * 128) + (uint32_t)((c ^ (r & 7)) << 4);
        CP_ASYNC16(sa, gp + (ll)r * rb);
    }
}

// ---------------------------------------------------------------------------
// Tensor-core GEMM: C[M,N] = A[M,K] @ B[N,K]^T (+per-column bias)
// MODE 0: split-bf16 3-pass (AhBh + AhBl + AlBh), fp32 accumulate.
// MODE 1: single-pass fp16 (Ahi/Bhi carry fp16 bits; Alo/Blo ignored).
// 3-stage cp.async ring, ONE barrier per K-chunk (prefetch issued pre-compute).
// Outputs: Cf (fp32); Chi+Clo (bf16 split); Chi alone (fp16 single).
// Batched via blockIdx.z (z1 = z/zdiv, z2 = z%zdiv); bias has z-strides too.
// ---------------------------------------------------------------------------
template <int MODE>
__global__ void __launch_bounds__(256)
gemm_tc(const __nv_bfloat16* __restrict__ Ahi, const __nv_bfloat16* __restrict__ Alo,
        const __nv_bfloat16* __restrict__ Bhi, const __nv_bfloat16* __restrict__ Blo,
        const float* __restrict__ bias,
        float* __restrict__ Cf, __nv_bfloat16* __restrict__ Chi, __nv_bfloat16* __restrict__ Clo,
        int K, ll lda, ll ldb, ll ldc,
        int zdiv, ll a_s1, ll a_s2, ll b_s1, ll b_s2, ll c_s1, ll c_s2,
        ll bias_s1, ll bias_s2)
{
    extern __shared__ char smem[];
    uint32_t sbase = smem_to_u32(smem);
    int tid = threadIdx.x;
    int lane = tid & 31;
    int wid = tid >> 5;
    int wm = wid & 1;          // M half (64 rows)
    int wn = wid >> 1;         // N quarter (32 cols)

    constexpr uint32_t NT_TILES = (MODE == 0) ? 4u : 2u;
    constexpr uint32_t STG = NT_TILES * TILE_SZ;
    constexpr uint32_t B_OFF = (MODE == 0) ? 2u * TILE_SZ : TILE_SZ;

    int z = blockIdx.z;
    int z1 = z / zdiv, z2 = z - z1 * zdiv;
    const __nv_bfloat16* Ah = Ahi + z1 * a_s1 + z2 * a_s2;
    const __nv_bfloat16* Al = (MODE == 0) ? Alo + z1 * a_s1 + z2 * a_s2 : nullptr;
    const __nv_bfloat16* Bh = Bhi + z1 * b_s1 + z2 * b_s2;
    const __nv_bfloat16* Bl = (MODE == 0) ? Blo + z1 * b_s1 + z2 * b_s2 : nullptr;
    const float* biasz = bias ? bias + z1 * bias_s1 + z2 * bias_s2 : nullptr;
    ll m0 = (ll)blockIdx.y * 128;
    ll n0 = (ll)blockIdx.x * 128;
    ll coff = z1 * c_s1 + z2 * c_s2 + m0 * ldc + n0;

    // ldmatrix lane geometry
    int rl = lane & 7;
    int sub = lane >> 3;
    int rowA = (sub & 1) * 8 + rl;   // row within 16-row m-tile
    int jA = sub >> 1;               // k-chunk select (0/1)
    int rowB = (sub >> 1) * 8 + rl;  // row within 16-row n-pair
    int jB = sub & 1;

    uint32_t aRowOff[4], bRowOff[2];
#pragma unroll
    for (int mi = 0; mi < 4; mi++)
        aRowOff[mi] = (uint32_t)((wm * 64 + mi * 16 + rowA) * 128);
#pragma unroll
    for (int p = 0; p < 2; p++)
        bRowOff[p] = (uint32_t)((wn * 32 + p * 16 + rowB) * 128);

    float acc[4][4][4];
#pragma unroll
    for (int mi = 0; mi < 4; mi++)
#pragma unroll
        for (int ni = 0; ni < 4; ni++)
#pragma unroll
            for (int q = 0; q < 4; q++) acc[mi][ni][q] = 0.f;

    int C = K >> 6;

    // prologue: load chunks 0, 1 into stages 0, 1
    {
        uint32_t st = sbase;
        tile_cp(Ah, lda, m0, 0, st, tid);
        tile_cp(Bh, ldb, n0, 0, st + B_OFF, tid);
        if (MODE == 0) {
            tile_cp(Al, lda, m0, 0, st + TILE_SZ, tid);
            tile_cp(Bl, ldb, n0, 0, st + B_OFF + TILE_SZ, tid);
        }
        CP_COMMIT();
    }
    if (C > 1) {
        uint32_t st = sbase + STG;
        tile_cp(Ah, lda, m0, 64, st, tid);
        tile_cp(Bh, ldb, n0, 64, st + B_OFF, tid);
        if (MODE == 0) {
            tile_cp(Al, lda, m0, 64, st + TILE_SZ, tid);
            tile_cp(Bl, ldb, n0, 64, st + B_OFF + TILE_SZ, tid);
        }
        CP_COMMIT();
    }

    int stage = 0;       // stage holding chunk c
    for (int c = 0; c < C; c++) {
        if (c + 1 < C) CP_WAIT1(); else CP_WAIT0();
        __syncthreads();   // all warps past compute c-1; chunk c visible to all

        // issue prefetch for chunk c+2 into stage (c+2)%3 (= stage of c-1)
        if (c + 2 < C) {
            int pst = stage + 2; if (pst >= 3) pst -= 3;
            uint32_t stn = sbase + (uint32_t)pst * STG;
            ll k0 = (ll)(c + 2) * 64;
            tile_cp(Ah, lda, m0, k0, stn, tid);
            tile_cp(Bh, ldb, n0, k0, stn + B_OFF, tid);
            if (MODE == 0) {
                tile_cp(Al, lda, m0, k0, stn + TILE_SZ, tid);
                tile_cp(Bl, ldb, n0, k0, stn + B_OFF + TILE_SZ, tid);
            }
            CP_COMMIT();
        }

        uint32_t st = sbase + (uint32_t)stage * STG;
#pragma unroll
        for (int kk = 0; kk < 4; kk++) {
            uint32_t chA = (uint32_t)(((kk * 2 + jA) ^ rl) << 4);
            uint32_t chB = (uint32_t)(((kk * 2 + jB) ^ rl) << 4);
            // pass 1: Ah x Bh
            uint32_t ah[4][4];
#pragma unroll
            for (int mi = 0; mi < 4; mi++)
                ldsm4(st + aRowOff[mi] + chA,
                      ah[mi][0], ah[mi][1], ah[mi][2], ah[mi][3]);
            uint32_t bh[4][2];
#pragma unroll
            for (int p = 0; p < 2; p++) {
                uint32_t r0, r1, r2, r3;
                ldsm4(st + B_OFF + bRowOff[p] + chB, r0, r1, r2, r3);
                bh[2 * p][0] = r0; bh[2 * p][1] = r1;
                bh[2 * p + 1][0] = r2; bh[2 * p + 1][1] = r3;
            }
#pragma unroll
            for (int mi = 0; mi < 4; mi++)
#pragma unroll
                for (int ni = 0; ni < 4; ni++) {
                    if (MODE == 0)
                        hmma_bf16(acc[mi][ni], ah[mi][0], ah[mi][1], ah[mi][2], ah[mi][3],
                                  bh[ni][0], bh[ni][1]);
                    else
                        hmma_fp16(acc[mi][ni], ah[mi][0], ah[mi][1], ah[mi][2], ah[mi][3],
                                  bh[ni][0], bh[ni][1]);
                }
            if (MODE == 0) {
                // pass 2: Ah x Bl
                uint32_t bl[4][2];
#pragma unroll
                for (int p = 0; p < 2; p++) {
                    uint32_t r0, r1, r2, r3;
                    ldsm4(st + B_OFF + TILE_SZ + bRowOff[p] + chB, r0, r1, r2, r3);
                    bl[2 * p][0] = r0; bl[2 * p][1] = r1;
                    bl[2 * p + 1][0] = r2; bl[2 * p + 1][1] = r3;
                }
#pragma unroll
                for (int mi = 0; mi < 4; mi++)
#pragma unroll
                    for (int ni = 0; ni < 4; ni++)
                        hmma_bf16(acc[mi][ni], ah[mi][0], ah[mi][1], ah[mi][2], ah[mi][3],
                                  bl[ni][0], bl[ni][1]);
                // pass 3: Al x Bh
                uint32_t al[4][4];
#pragma unroll
                for (int mi = 0; mi < 4; mi++)
                    ldsm4(st + TILE_SZ + aRowOff[mi] + chA,
                          al[mi][0], al[mi][1], al[mi][2], al[mi][3]);
#pragma unroll
                for (int mi = 0; mi < 4; mi++)
#pragma unroll
                    for (int ni = 0; ni < 4; ni++)
                        hmma_bf16(acc[mi][ni], al[mi][0], al[mi][1], al[mi][2], al[mi][3],
                                  bh[ni][0], bh[ni][1]);
            }
        }

        stage++; if (stage >= 3) stage -= 3;
    }

    // ---- Epilogue: acc -> smem staging -> coalesced global ----
    __syncthreads();   // all warps done reading stage smem before pad reuse
    float* ep = (float*)smem;
    {
        int gr = lane >> 2, gc = lane & 3;
#pragma unroll
        for (int mi = 0; mi < 4; mi++)
#pragma unroll
            for (int ni = 0; ni < 4; ni++) {
                int row = wm * 64 + mi * 16 + gr;
                int col = wn * 32 + ni * 8 + gc * 2;
                *(float2*)&ep[row * EP_PITCH + col] =
                    make_float2(acc[mi][ni][0], acc[mi][ni][1]);
                *(float2*)&ep[(row + 8) * EP_PITCH + col] =
                    make_float2(acc[mi][ni][2], acc[mi][ni][3]);
            }
    }
    __syncthreads();

    {
        int lc = tid & 31;        // col group (x4)
        int rbase = tid >> 5;     // 0..7
        float4 bv = make_float4(0.f, 0.f, 0.f, 0.f);
        if (biasz) bv = *(const float4*)(biasz + n0 + lc * 4);
#pragma unroll
        for (int i = 0; i < 16; i++) {
            int row = rbase + i * 8;
            float4 v = *(float4*)&ep[row * EP_PITCH + lc * 4];
            v.x += bv.x; v.y += bv.y; v.z += bv.z; v.w += bv.w;
            ll off = coff + (ll)row * ldc + lc * 4;
            if (Cf) *(float4*)(Cf + off) = v;
            if (Chi) {
                if (Clo) {
                    // bf16 split output
                    __nv_bfloat16 h0 = __float2bfloat16(v.x);
                    __nv_bfloat16 h1 = __float2bfloat16(v.y);
                    __nv_bfloat16 h2 = __float2bfloat16(v.z);
                    __nv_bfloat16 h3 = __float2bfloat16(v.w);
                    __nv_bfloat16 l0 = __float2bfloat16(v.x - __bfloat162float(h0));
                    __nv_bfloat16 l1 = __float2bfloat16(v.y - __bfloat162float(h1));
                    __nv_bfloat16 l2 = __float2bfloat16(v.z - __bfloat162float(h2));
                    __nv_bfloat16 l3 = __float2bfloat16(v.w - __bfloat162float(h3));
                    uint2 hv, lv;
                    __nv_bfloat16* hp = (__nv_bfloat16*)&hv;
                    __nv_bfloat16* lp = (__nv_bfloat16*)&lv;
                    hp[0] = h0; hp[1] = h1; hp[2] = h2; hp[3] = h3;
                    lp[0] = l0; lp[1] = l1; lp[2] = l2; lp[3] = l3;
                    *(uint2*)(Chi + off) = hv;
                    *(uint2*)(Clo + off) = lv;
                } else {
                    // fp16 single output
                    uint2 hv;
                    __half* hp = (__half*)&hv;
                    hp[0] = __float2half(v.x);
                    hp[1] = __float2half(v.y);
                    hp[2] = __float2half(v.z);
                    hp[3] = __float2half(v.w);
                    *(uint2*)((__half*)Chi + off) = hv;
                }
            }
        }
    }
}

// ---------------------------------------------------------------------------
// Fused BN folding for all three weight sets.
// ---------------------------------------------------------------------------
__global__ void fold_all(const float* __restrict__ W_phi,
                         const float* __restrict__ pg, const float* __restrict__ pb,
                         const float* __restrict__ pm, const float* __restrict__ pv,
                         const float* __restrict__ W_psi,
                         const float* __restrict__ sg, const float* __restrict__ sb,
                         const float* __restrict__ sm, const float* __restrict__ sv,
                         const float* __restrict__ W_red,
                         const float* __restrict__ rg, const float* __restrict__ rb,
                         const float* __restrict__ rm, const float* __restrict__ rv,
                         float* __restrict__ Wphi_f, float* __restrict__ bphi,
                         float* __restrict__ Wpsi_f,
                         __half* __restrict__ Wred_f16, float* __restrict__ bred)
{
    int blk = blockIdx.x;
    int tid = threadIdx.x;
    __shared__ float red[256];
    if (blk < HP) {
        int o = blk;
        float partial = 0.f;
        const float* wrow = W_phi + (ll)o * D_;
        float* wfrow = Wphi_f + (ll)o * D_;
        for (int d = tid; d < D_; d += 256) {
            float sc = pg[d] * rsqrtf(pv[d] + 1e-5f);
            float sh = pb[d] - pm[d] * sc;
            float w = wrow[d];
            wfrow[d] = w * sc;
            partial += w * sh;
        }
        red[tid] = partial;
        __syncthreads();
        for (int s = 128; s > 0; s >>= 1) {
            if (tid < s) red[tid] += red[tid + s];
            __syncthreads();
        }
        if (tid == 0) bphi[o] = red[0];
    } else if (blk < HP + PROJ) {
        int o = blk - HP;
        const float* wrow = W_psi + (ll)o * D_;
        float* wfrow = Wpsi_f + (ll)o * D_;
        for (int d = tid; d < D_; d += 256) {
            float sc = sg[d] * rsqrtf(sv[d] + 1e-5f);
            wfrow[d] = wrow[d] * sc;
        }
    } else {
        int o = blk - HP - PROJ;
        float partial = 0.f;
        const float* wrow = W_red + (ll)o * HD;
        __half* wfr = Wred_f16 + (ll)o * HD;
        for (int d = tid; d < HD; d += 256) {
            float sc = rg[d] * rsqrtf(rv[d] + 1e-5f);
            float sh = rb[d] - rm[d] * sc;
            float w = wrow[d];
            wfr[d] = __float2half(w * sc);
            partial += w * sh;
        }
        red[tid] = partial;
        __syncthreads();
        for (int s = 128; s > 0; s >>= 1) {
            if (tid < s) red[tid] += red[tid + s];
            __syncthreads();
        }
        if (tid == 0) bred[o] = red[0];
    }
}

// ---------------------------------------------------------------------------
// Fused transpose of both folded weights: fp32 [R,C] -> split bf16 [C,R].
// ---------------------------------------------------------------------------
__global__ void __launch_bounds__(256)
transpose_both(const float* __restrict__ wphi, __nv_bfloat16* __restrict__ phi_hi,
               __nv_bfloat16* __restrict__ phi_lo,
               const float* __restrict__ wpsi, __nv_bfloat16* __restrict__ psi_hi,
               __nv_bfloat16* __restrict__ psi_lo)
{
    __shared__ float t[32][33];
    const float* in;
    __nv_bfloat16 *ohi, *olo;
    int R, r0;
    if (blockIdx.x < HP / 32) {
        in = wphi; ohi = phi_hi; olo = phi_lo; R = HP; r0 = blockIdx.x * 32;
    } else {
        in = wpsi; ohi = psi_hi; olo = psi_lo; R = PROJ;
        r0 = (blockIdx.x - HP / 32) * 32;
    }
    int c0 = blockIdx.y * 32;
#pragma unroll
    for (int j = 0; j < 4; j++) {
        int r = threadIdx.y + j * 8;
        t[r][threadIdx.x] = in[(ll)(r0 + r) * D_ + c0 + threadIdx.x];
    }
    __syncthreads();
#pragma unroll
    for (int j = 0; j < 4; j++) {
        int c = threadIdx.y + j * 8;
        float v = t[threadIdx.x][c];
        __nv_bfloat16 hi = __float2bfloat16(v);
        ll off = (ll)(c0 + c) * R + r0 + threadIdx.x;
        ohi[off] = hi;
        olo[off] = __float2bfloat16(v - __bfloat162float(hi));
    }
}

// ---------------------------------------------------------------------------
// u[g][d] = sum_p bphi[g*PROJ+p] * Wpsi_f[p][d]
// ---------------------------------------------------------------------------
__global__ void __launch_bounds__(512)
u_kernel(const float* __restrict__ bphi, const float* __restrict__ wpsi,
         float* __restrict__ u)
{
    int g = blockIdx.x;
    int d = threadIdx.x;
    float acc = 0.f;
    const float* bp = bphi + g * PROJ;
    for (int p = 0; p < PROJ; p++)
        acc += bp[p] * wpsi[(ll)p * D_ + d];
    u[g * D_ + d] = acc;
}

// ---------------------------------------------------------------------------
// cb[g][b*TK+k] = sum_d h[b][k][d] * u[g][d].  One warp per (b,k) row.
// ---------------------------------------------------------------------------
__global__ void __launch_bounds__(256)
colbias_kernel(const float* __restrict__ h, const float* __restrict__ u,
               float* __restrict__ cb)
{
    __shared__ float us[NH * D_];
    int tid = threadIdx.x;
    for (int i = tid; i < NH * D_; i += 256) us[i] = u[i];
    __syncthreads();
    int w = tid >> 5, l = tid & 31;
    ll r = (ll)blockIdx.x * 8 + w;          // (b,k) row in [0, B_*TK)
    const float* row = h + r * D_;
    float a0 = 0.f, a1 = 0.f, a2 = 0.f, a3 = 0.f;
    for (int i = l; i < D_; i += 32) {
        float v = row[i];
        a0 += v * us[i];
        a1 += v * us[D_ + i];
        a2 += v * us[2 * D_ + i];
        a3 += v * us[3 * D_ + i];
    }
#pragma unroll
    for (int s = 16; s > 0; s >>= 1) {
        a0 += __shfl_xor_sync(0xFFFFFFFF, a0, s);
        a1 += __shfl_xor_sync(0xFFFFFFFF, a1, s);
        a2 += __shfl_xor_sync(0xFFFFFFFF, a2, s);
        a3 += __shfl_xor_sync(0xFFFFFFFF, a3, s);
    }
    if (l == 0) {
        const ll BT = (ll)B_ * TK;
        cb[r] = a0;
        cb[BT + r] = a1;
        cb[2 * BT + r] = a2;
        cb[3 * BT + r] = a3;
    }
}

// ---------------------------------------------------------------------------
// Elementwise fp32 -> bf16 hi/lo split (for s)
// ---------------------------------------------------------------------------
__global__ void __launch_bounds__(256)
split_kernel(const float* __restrict__ x, __nv_bfloat16* __restrict__ hi,
             __nv_bfloat16* __restrict__ lo, ll n4)
{
    ll i = (ll)blockIdx.x * 256 + threadIdx.x;
    if (i >= n4) return;
    float4 v = *(const float4*)(x + i * 4);
    __nv_bfloat16 h0 = __float2bfloat16(v.x);
    __nv_bfloat16 h1 = __float2bfloat16(v.y);
    __nv_bfloat16 h2 = __float2bfloat16(v.z);
    __nv_bfloat16 h3 = __float2bfloat16(v.w);
    uint2 hv, lv;
    __nv_bfloat16* hp = (__nv_bfloat16*)&hv;
    __nv_bfloat16* lp = (__nv_bfloat16*)&lv;
    hp[0] = h0; hp[1] = h1; hp[2] = h2; hp[3] = h3;
    lp[0] = __float2bfloat16(v.x - __bfloat162float(h0));
    lp[1] = __float2bfloat16(v.y - __bfloat162float(h1));
    lp[2] = __float2bfloat16(v.z - __bfloat162float(h2));
    lp[3] = __float2bfloat16(v.w - __bfloat162float(h3));
    *(uint2*)(hi + i * 4) = hv;
    *(uint2*)(lo + i * 4) = lv;
}

// ---------------------------------------------------------------------------
// Fused h prep, vectorized: one read of h produces h_hi/h_lo (row-major,
// uint2 stores) AND ht fp16 (transposed [b][d][k], uint2 stores).
// ---------------------------------------------------------------------------
__global__ void __launch_bounds__(256)
prep_h(const float* __restrict__ h, __nv_bfloat16* __restrict__ hhi,
       __nv_bfloat16* __restrict__ hlo, __half* __restrict__ tf)
{
    __shared__ float t[32][33];
    int b = blockIdx.z;
    int k0 = blockIdx.x * 32;
    int d0 = blockIdx.y * 32;
    int tx = threadIdx.x;     // 0..7  (d quad)
    int ty = threadIdx.y;     // 0..31 (k)
    const float* hb = h + (ll)b * TK * D_;

    float4 v = *(const float4*)(hb + (ll)(k0 + ty) * D_ + d0 + tx * 4);
    t[ty][tx * 4 + 0] = v.x;
    t[ty][tx * 4 + 1] = v.y;
    t[ty][tx * 4 + 2] = v.z;
    t[ty][tx * 4 + 3] = v.w;

    {
        __nv_bfloat16 h0 = __float2bfloat16(v.x);
        __nv_bfloat16 h1 = __float2bfloat16(v.y);
        __nv_bfloat16 h2 = __float2bfloat16(v.z);
        __nv_bfloat16 h3 = __float2bfloat16(v.w);
        uint2 hv, lv;
        __nv_bfloat16* hp = (__nv_bfloat16*)&hv;
        __nv_bfloat16* lp = (__nv_bfloat16*)&lv;
        hp[0] = h0; hp[1] = h1; hp[2] = h2; hp[3] = h3;
        lp[0] = __float2bfloat16(v.x - __bfloat162float(h0));
        lp[1] = __float2bfloat16(v.y - __bfloat162float(h1));
        lp[2] = __float2bfloat16(v.z - __bfloat162float(h2));
        lp[3] = __float2bfloat16(v.w - __bfloat162float(h3));
        ll off = (ll)b * TK * D_ + (ll)(k0 + ty) * D_ + d0 + tx * 4;
        *(uint2*)(hhi + off) = hv;
        *(uint2*)(hlo + off) = lv;
    }
    __syncthreads();

    {
        float a0 = t[tx * 4 + 0][ty];
        float a1 = t[tx * 4 + 1][ty];
        float a2 = t[tx * 4 + 2][ty];
        float a3 = t[tx * 4 + 3][ty];
        __half2 p01 = __floats2half2_rn(a0, a1);
        __half2 p23 = __floats2half2_rn(a2, a3);
        uint2 hv;
        hv.x = *(uint32_t*)&p01;
        hv.y = *(uint32_t*)&p23;
        *(uint2*)(tf + (ll)b * D_ * TK + (ll)(d0 + ty) * TK + k0 + tx * 4) = hv;
    }
}

// ---------------------------------------------------------------------------
// Row softmax, in place, + fp16 copy. Warp-per-row, 8 rows per 256-thread
// block, zero block barriers, MLP=8 float4 loads per thread.
// ---------------------------------------------------------------------------
__global__ void __launch_bounds__(256)
softmax_kernel(float* __restrict__ a, __half* __restrict__ af16)
{
    int w = threadIdx.x >> 5, lane = threadIdx.x & 31;
    ll row = (ll)blockIdx.x * 8 + w;
    float* rp = a + row * TK;

    float4 x[8];
#pragma unroll
    for (int i = 0; i < 8; i++)
        x[i] = *(float4*)(rp + i * 128 + lane * 4);

    float m = -INFINITY;
#pragma unroll
    for (int i = 0; i < 8; i++)
        m = fmaxf(m, fmaxf(fmaxf(x[i].x, x[i].y), fmaxf(x[i].z, x[i].w)));
#pragma unroll
    for (int s = 16; s > 0; s >>= 1)
        m = fmaxf(m, __shfl_xor_sync(0xFFFFFFFF, m, s));

    float sum = 0.f;
#pragma unroll
    for (int i = 0; i < 8; i++) {
        x[i].x = __expf(x[i].x - m);
        x[i].y = __expf(x[i].y - m);
        x[i].z = __expf(x[i].z - m);
        x[i].w = __expf(x[i].w - m);
        sum += (x[i].x + x[i].y) + (x[i].z + x[i].w);
    }
#pragma unroll
    for (int s = 16; s > 0; s >>= 1)
        sum += __shfl_xor_sync(0xFFFFFFFF, sum, s);
    float inv = 1.f / sum;

    __half* fp = af16 + row * TK;
#pragma unroll
    for (int i = 0; i < 8; i++) {
        float4 o = make_float4(x[i].x * inv, x[i].y * inv,
                               x[i].z * inv, x[i].w * inv);
        *(float4*)(rp + i * 128 + lane * 4) = o;
        __half2 h01 = __floats2half2_rn(o.x, o.y);
        __half2 h23 = __floats2half2_rn(o.z, o.w);
        uint2 hv;
        hv.x = *(uint32_t*)&h01;
        hv.y = *(uint32_t*)&h23;
        *(uint2*)(fp + i * 128 + lane * 4) = hv;
    }
}

// ---------------------------------------------------------------------------
extern "C" void kernel_launch(void* const* d_in, const int* in_sizes, int n_in,
                              void* d_out, int out_size)
{
    const float* s_in      = (const float*)d_in[0];
    const float* h_in      = (const float*)d_in[1];
    const float* phi_gamma = (const float*)d_in[2];
    const float* phi_beta  = (const float*)d_in[3];
    const float* phi_mean  = (const float*)d_in[4];
    const float* phi_var   = (const float*)d_in[5];
    const float* W_phi     = (const float*)d_in[6];
    const float* psi_gamma = (const float*)d_in[7];
    const float* psi_beta  = (const float*)d_in[8];
    const float* psi_mean  = (const float*)d_in[9];
    const float* psi_var   = (const float*)d_in[10];
    const float* W_psi     = (const float*)d_in[11];
    const float* red_gamma = (const float*)d_in[12];
    const float* red_beta  = (const float*)d_in[13];
    const float* red_mean  = (const float*)d_in[14];
    const float* red_var   = (const float*)d_in[15];
    const float* W_red     = (const float*)d_in[16];

    float* a_out = (float*)d_out;               // [H, B, Tq, Tk]
    float* c_out = a_out + A_ELEMS;             // [B, Tq, D]

    __nv_bfloat16 *s_hi, *s_lo, *h_hi, *h_lo;
    __nv_bfloat16 *ms_hi, *ms_lo;
    __nv_bfloat16 *WphiT_hi, *WphiT_lo, *WpsiT_hi, *WpsiT_lo, *Gt_hi, *Gt_lo;
    __half *ht_f16, *a_f16, *ctx_f16, *Wred_f16;
    float *bphi, *bred, *Wphi_f, *Wpsi_f, *u_dev, *cb;
    cudaGetSymbolAddress((void**)&s_hi, g_s_hi);   cudaGetSymbolAddress((void**)&s_lo, g_s_lo);
    cudaGetSymbolAddress((void**)&h_hi, g_h_hi);   cudaGetSymbolAddress((void**)&h_lo, g_h_lo);
    cudaGetSymbolAddress((void**)&ht_f16, g_ht_f16);
    cudaGetSymbolAddress((void**)&ms_hi, g_ms_hi); cudaGetSymbolAddress((void**)&ms_lo, g_ms_lo);
    cudaGetSymbolAddress((void**)&a_f16, g_a_f16);
    cudaGetSymbolAddress((void**)&ctx_f16, g_ctx_f16);
    cudaGetSymbolAddress((void**)&Wred_f16, g_Wred_f16);
    cudaGetSymbolAddress((void**)&WphiT_hi, g_WphiT_hi); cudaGetSymbolAddress((void**)&WphiT_lo, g_WphiT_lo);
    cudaGetSymbolAddress((void**)&WpsiT_hi, g_WpsiT_hi); cudaGetSymbolAddress((void**)&WpsiT_lo, g_WpsiT_lo);
    cudaGetSymbolAddress((void**)&Gt_hi, g_Gt_hi); cudaGetSymbolAddress((void**)&Gt_lo, g_Gt_lo);
    cudaGetSymbolAddress((void**)&Wphi_f, g_Wphi_f); cudaGetSymbolAddress((void**)&Wpsi_f, g_Wpsi_f);
    cudaGetSymbolAddress((void**)&u_dev, g_u); cudaGetSymbolAddress((void**)&cb, g_cb);
    cudaGetSymbolAddress((void**)&bphi, g_bphi);
    cudaGetSymbolAddress((void**)&bred, g_bred);

    cudaFuncSetAttribute(gemm_tc<0>, cudaFuncAttributeMaxDynamicSharedMemorySize,
                         SMEM_MODE0);
    cudaFuncSetAttribute(gemm_tc<1>, cudaFuncAttributeMaxDynamicSharedMemorySize,
                         SMEM_MODE1);

    // ---- streams & events (falls back to serial) ----
    cudaStream_t sA = 0;
    if (cudaStreamCreateWithFlags(&sA, cudaStreamNonBlocking) != cudaSuccess) sA = 0;
    cudaEvent_t evF, evSplit, evFold, evPrep, evS1, evC1;
    cudaEventCreateWithFlags(&evF,     cudaEventDisableTiming);
    cudaEventCreateWithFlags(&evSplit, cudaEventDisableTiming);
    cudaEventCreateWithFlags(&evFold,  cudaEventDisableTiming);
    cudaEventCreateWithFlags(&evPrep,  cudaEventDisableTiming);
    cudaEventCreateWithFlags(&evS1,    cudaEventDisableTiming);
    cudaEventCreateWithFlags(&evC1,    cudaEventDisableTiming);

    // fork
    cudaEventRecord(evF, 0);
    cudaStreamWaitEvent(sA, evF, 0);

    // ---- side stream: input conversions + bias pipeline ----
    split_kernel<<<(int)(((ll)B_ * TQ * D_ / 4 + 255) / 256), 256, 0, sA>>>(
        s_in, s_hi, s_lo, (ll)B_ * TQ * D_ / 4);
    cudaEventRecord(evSplit, sA);
    prep_h<<<dim3(TK / 32, D_ / 32, B_), dim3(8, 32), 0, sA>>>(h_in, h_hi, h_lo, ht_f16);

    // ---- main stream: weight pipeline ----
    fold_all<<<HP + PROJ + D_, 256, 0, 0>>>(
        W_phi, phi_gamma, phi_beta, phi_mean, phi_var,
        W_psi, psi_gamma, psi_beta, psi_mean, psi_var,
        W_red, red_gamma, red_beta, red_mean, red_var,
        Wphi_f, bphi, Wpsi_f, Wred_f16, bred);
    cudaEventRecord(evFold, 0);
    transpose_both<<<dim3((HP + PROJ) / 32, D_ / 32), dim3(32, 8), 0, 0>>>(
        Wphi_f, WphiT_hi, WphiT_lo, Wpsi_f, WpsiT_hi, WpsiT_lo);

    // side: u & colbias need fold_all's bphi/Wpsi_f
    cudaStreamWaitEvent(sA, evFold, 0);
    u_kernel<<<NH, 512, 0, sA>>>(bphi, Wpsi_f, u_dev);
    colbias_kernel<<<(int)((ll)B_ * TK / 8), 256, 0, sA>>>(h_in, u_dev, cb);
    cudaEventRecord(evPrep, sA);

    // main: Gt GEMM
    gemm_tc<0><<<dim3(4, 4, NH), 256, SMEM_MODE0, 0>>>(
        WpsiT_hi, WpsiT_lo, WphiT_hi, WphiT_lo, nullptr,
        nullptr, Gt_hi, Gt_lo,
        PROJ, PROJ, HP, D_,
        1, 0, 0, (ll)PROJ, 0, (ll)D_ * D_, 0, 0, 0);

    // ---- serial heavy chain on main ----
    cudaStreamWaitEvent(0, evSplit, 0);
    // sG = s @ Gt^T : [8192, 2048], K=512 -> split out (ms buffers)
    gemm_tc<0><<<dim3(HP / 128, (B_ * TQ) / 128, 1), 256, SMEM_MODE0, 0>>>(
        s_hi, s_lo, Gt_hi, Gt_lo, nullptr,
        nullptr, ms_hi, ms_lo,
        D_, D_, D_, HP,
        1, 0, 0, 0, 0, 0, 0, 0, 0);

    cudaStreamWaitEvent(0, evPrep, 0);
    // logits e[g,b,q,k] = sG_g[b,q,:] . h[b,k,:] + cb[g,b,k] -> fp32 a_out (FULL)
    gemm_tc<0><<<dim3(TK / 128, TQ / 128, B_ * NH), 256, SMEM_MODE0, 0>>>(
        ms_hi, ms_lo, h_hi, h_lo, cb,
        a_out, nullptr, nullptr,
        D_, HP, D_, TK,
        NH,
        (ll)TQ * HP, (ll)PROJ,
        (ll)TK * D_, 0,
        (ll)TQ * TK, (ll)B_ * TQ * TK,
        (ll)TK, (ll)B_ * TK);

    // ---- tail: softmax/ctx split by head-half; softmax_h2 overlaps ctx_h1 ----
    const ll HBT = 2LL * B_ * TQ * TK;   // a elements per head-half (g pair)

    // softmax half 1 (g = 0,1) on main
    softmax_kernel<<<2 * B_ * TQ / 8, 256, 0, 0>>>(a_out, a_f16);
    cudaEventRecord(evS1, 0);

    // side: ctx half 1 (g = 0,1) — tensor-bound, 96 KB smem
    cudaStreamWaitEvent(sA, evS1, 0);
    gemm_tc<1><<<dim3(D_ / 128, TQ / 128, B_ * 2), 256, SMEM_MODE1, sA>>>(
        (const __nv_bfloat16*)a_f16, nullptr,
        (const __nv_bfloat16*)ht_f16, nullptr, nullptr,
        nullptr, (__nv_bfloat16*)ctx_f16, nullptr,
        TK, TK, TK, HD,
        2,
        (ll)TQ * TK, (ll)B_ * TQ * TK,
        (ll)D_ * TK, 0,
        (ll)TQ * HD, (ll)D_,
        0, 0);
    cudaEventRecord(evC1, sA);

    // main: softmax half 2 (g = 2,3) — 0 smem, memory-bound, co-resides
    softmax_kernel<<<2 * B_ * TQ / 8, 256, 0, 0>>>(a_out + HBT, a_f16 + HBT);
    // main: ctx half 2 (g = 2,3)
    gemm_tc<1><<<dim3(D_ / 128, TQ / 128, B_ * 2), 256, SMEM_MODE1, 0>>>(
        (const __nv_bfloat16*)(a_f16 + HBT), nullptr,
        (const __nv_bfloat16*)ht_f16, nullptr, nullptr,
        nullptr, (__nv_bfloat16*)(ctx_f16 + 2 * D_), nullptr,
        TK, TK, TK, HD,
        2,
        (ll)TQ * TK, (ll)B_ * TQ * TK,
        (ll)D_ * TK, 0,
        (ll)TQ * HD, (ll)D_,
        0, 0);

    // join, then final reduce GEMM
    cudaStreamWaitEvent(0, evC1, 0);
    gemm_tc<1><<<dim3(D_ / 128, (B_ * TQ) / 128, 1), 256, SMEM_MODE1, 0>>>(
        (const __nv_bfloat16*)ctx_f16, nullptr,
        (const __nv_bfloat16*)Wred_f16, nullptr, bred,
        c_out, nullptr, nullptr,
        HD, HD, HD, D_,
        1, 0, 0, 0, 0, 0, 0, 0, 0);
    // (streams/events intentionally not destroyed; kernel_launch is called
    //  only a handful of times outside the timed graph replay)
}

// round 15
// speedup vs baseline: 1.4729x; 1.4729x over previous
#include <cuda_runtime.h>
#include <cuda_bf16.h>
#include <cuda_fp16.h>
#include <math.h>
#include <stdint.h>

// Problem constants
#define B_   32
#define TQ   256
#define TK   1024
#define D_   512
#define NH   4
#define PROJ 512
#define HP   (NH * PROJ)      // 2048
#define HD   (NH * D_)        // 2048
#define A_ELEMS (4LL * 32 * 256 * 1024)   // 33554432

typedef long long ll;

// ---------------------------------------------------------------------------
// Scratch (static device arrays — sanctioned workaround for no-alloc rule)
// ---------------------------------------------------------------------------
__device__ __align__(128) __nv_bfloat16 g_s_hi[(size_t)B_ * TQ * D_];
__device__ __align__(128) __nv_bfloat16 g_s_lo[(size_t)B_ * TQ * D_];
__device__ __align__(128) __nv_bfloat16 g_h_hi[(size_t)B_ * TK * D_];
__device__ __align__(128) __nv_bfloat16 g_h_lo[(size_t)B_ * TK * D_];
__device__ __align__(128) __half        g_ht_f16[(size_t)B_ * D_ * TK];
__device__ __align__(128) __nv_bfloat16 g_ms_hi[(size_t)B_ * TQ * HP];   // sG
__device__ __align__(128) __nv_bfloat16 g_ms_lo[(size_t)B_ * TQ * HP];
__device__ __align__(128) __half        g_a_f16[(size_t)A_ELEMS];
__device__ __align__(128) __half        g_ctx_f16[(size_t)B_ * TQ * HD];
__device__ __align__(128) __half        g_Wred_f16[(size_t)D_ * HD];
// G-decomposition scratch
__device__ __align__(128) float         g_Wphi_f[(size_t)HP * D_];
__device__ __align__(128) float         g_Wpsi_f[(size_t)PROJ * D_];
__device__ __align__(128) __nv_bfloat16 g_WphiT_hi[(size_t)D_ * HP];
__device__ __align__(128) __nv_bfloat16 g_WphiT_lo[(size_t)D_ * HP];
__device__ __align__(128) __nv_bfloat16 g_WpsiT_hi[(size_t)D_ * PROJ];
__device__ __align__(128) __nv_bfloat16 g_WpsiT_lo[(size_t)D_ * PROJ];
__device__ __align__(128) __nv_bfloat16 g_Gt_hi[(size_t)NH * D_ * D_];
__device__ __align__(128) __nv_bfloat16 g_Gt_lo[(size_t)NH * D_ * D_];
__device__ __align__(128) float         g_u[(size_t)NH * D_];
__device__ __align__(128) float         g_cb[(size_t)NH * B_ * TK];
__device__ float g_bphi[HP];
__device__ float g_bred[D_];

// ---------------------------------------------------------------------------
// Helpers
// ---------------------------------------------------------------------------
__device__ __forceinline__ uint32_t smem_to_u32(const void* p) {
    uint32_t a;
    asm("{ .reg .u64 t; cvta.to.shared.u64 t, %1; cvt.u32.u64 %0, t; }"
        : "=r"(a) : "l"(p));
    return a;
}

__device__ __forceinline__ void ldsm4(uint32_t addr, uint32_t& r0, uint32_t& r1,
                                      uint32_t& r2, uint32_t& r3)
{
    asm volatile("ldmatrix.sync.aligned.m8n8.x4.shared.b16 {%0,%1,%2,%3}, [%4];"
                 : "=r"(r0), "=r"(r1), "=r"(r2), "=r"(r3) : "r"(addr));
}

__device__ __forceinline__ void hmma_bf16(float* c, uint32_t a0, uint32_t a1,
                                          uint32_t a2, uint32_t a3,
                                          uint32_t b0, uint32_t b1)
{
    asm volatile(
        "mma.sync.aligned.m16n8k16.row.col.f32.bf16.bf16.f32 "
        "{%0,%1,%2,%3}, {%4,%5,%6,%7}, {%8,%9}, {%0,%1,%2,%3};"
        : "+f"(c[0]), "+f"(c[1]), "+f"(c[2]), "+f"(c[3])
        : "r"(a0), "r"(a1), "r"(a2), "r"(a3), "r"(b0), "r"(b1));
}

__device__ __forceinline__ void hmma_fp16(float* c, uint32_t a0, uint32_t a1,
                                          uint32_t a2, uint32_t a3,
                                          uint32_t b0, uint32_t b1)
{
    asm volatile(
        "mma.sync.aligned.m16n8k16.row.col.f32.f16.f16.f32 "
        "{%0,%1,%2,%3}, {%4,%5,%6,%7}, {%8,%9}, {%0,%1,%2,%3};"
        : "+f"(c[0]), "+f"(c[1]), "+f"(c[2]), "+f"(c[3])
        : "r"(a0), "r"(a1), "r"(a2), "r"(a3), "r"(b0), "r"(b1));
}

#define CP_ASYNC16(sa, ga) \
    asm volatile("cp.async.cg.shared.global [%0], [%1], 16;" :: "r"(sa), "l"(ga))
#define CP_COMMIT() asm volatile("cp.async.commit_group;" ::: "memory")
#define CP_WAIT1()  asm volatile("cp.async.wait_group 1;" ::: "memory")
#define CP_WAIT0()  asm volatile("cp.async.wait_group 0;" ::: "memory")

// ---------------------------------------------------------------------------
// smem: 3-stage ring.
// MODE 0 (3-pass bf16 pairs): 3 stages x {Ahi,Alo,Bhi,Blo} = 192 KB
// MODE 1 (1-pass fp16):       3 stages x {A,B} = 96 KB
// ---------------------------------------------------------------------------
#define TILE_SZ 16384
#define EP_PITCH 132
#define SMEM_MODE0 (12 * TILE_SZ)          // 196608
#define SMEM_MODE1 (6 * TILE_SZ)           // 98304 (>= 67584 epilogue pad)

// Load one 128x64 bf16/fp16 tile (rows row0.., cols k0..k0+63) into swizzled smem.
__device__ __forceinline__ void tile_cp(const __nv_bfloat16* __restrict__ g,
                                        ll stride, ll row0, ll k0,
                                        uint32_t stile, int tid)
{
    int c = tid & 7;           // 16B chunk within row
    int r0 = tid >> 3;         // 0..31
    const char* gp = (const char*)(g + row0 * stride + k0 + c * 8);
    ll rb = stride * 2;
#pragma unroll
    for (int i = 0; i < 4; i++) {
        int r = r0 + i * 32;
        uint32_t sa = stile + (uint32_t)(r * 128) + (uint32_t)((c ^ (r & 7)) << 4);
        CP_ASYNC16(sa, gp + (ll)r * rb);
    }
}

// ---------------------------------------------------------------------------
// Tensor-core GEMM: C[M,N] = A[M,K] @ B[N,K]^T (+per-column bias)
// MODE 0: split-bf16 3-pass (AhBh + AhBl + AlBh), fp32 accumulate.
// MODE 1: single-pass fp16 (Ahi/Bhi carry fp16 bits; Alo/Blo ignored).
// 3-stage cp.async ring, ONE barrier per K-chunk (prefetch issued pre-compute).
// Outputs: Cf (fp32); Chi+Clo (bf16 split); Chi alone (fp16 single).
// Batched via blockIdx.z (z1 = z/zdiv, z2 = z%zdiv); bias has z-strides too.
// ---------------------------------------------------------------------------
template <int MODE>
__global__ void __launch_bounds__(256)
gemm_tc(const __nv_bfloat16* __restrict__ Ahi, const __nv_bfloat16* __restrict__ Alo,
        const __nv_bfloat16* __restrict__ Bhi, const __nv_bfloat16* __restrict__ Blo,
        const float* __restrict__ bias,
        float* __restrict__ Cf, __nv_bfloat16* __restrict__ Chi, __nv_bfloat16* __restrict__ Clo,
        int K, ll lda, ll ldb, ll ldc,
        int zdiv, ll a_s1, ll a_s2, ll b_s1, ll b_s2, ll c_s1, ll c_s2,
        ll bias_s1, ll bias_s2)
{
    extern __shared__ char smem[];
    uint32_t sbase = smem_to_u32(smem);
    int tid = threadIdx.x;
    int lane = tid & 31;
    int wid = tid >> 5;
    int wm = wid & 1;          // M half (64 rows)
    int wn = wid >> 1;         // N quarter (32 cols)

    constexpr uint32_t NT_TILES = (MODE == 0) ? 4u : 2u;
    constexpr uint32_t STG = NT_TILES * TILE_SZ;
    constexpr uint32_t B_OFF = (MODE == 0) ? 2u * TILE_SZ : TILE_SZ;

    int z = blockIdx.z;
    int z1 = z / zdiv, z2 = z - z1 * zdiv;
    const __nv_bfloat16* Ah = Ahi + z1 * a_s1 + z2 * a_s2;
    const __nv_bfloat16* Al = (MODE == 0) ? Alo + z1 * a_s1 + z2 * a_s2 : nullptr;
    const __nv_bfloat16* Bh = Bhi + z1 * b_s1 + z2 * b_s2;
    const __nv_bfloat16* Bl = (MODE == 0) ? Blo + z1 * b_s1 + z2 * b_s2 : nullptr;
    const float* biasz = bias ? bias + z1 * bias_s1 + z2 * bias_s2 : nullptr;
    ll m0 = (ll)blockIdx.y * 128;
    ll n0 = (ll)blockIdx.x * 128;
    ll coff = z1 * c_s1 + z2 * c_s2 + m0 * ldc + n0;

    // ldmatrix lane geometry
    int rl = lane & 7;
    int sub = lane >> 3;
    int rowA = (sub & 1) * 8 + rl;   // row within 16-row m-tile
    int jA = sub >> 1;               // k-chunk select (0/1)
    int rowB = (sub >> 1) * 8 + rl;  // row within 16-row n-pair
    int jB = sub & 1;

    uint32_t aRowOff[4], bRowOff[2];
#pragma unroll
    for (int mi = 0; mi < 4; mi++)
        aRowOff[mi] = (uint32_t)((wm * 64 + mi * 16 + rowA) * 128);
#pragma unroll
    for (int p = 0; p < 2; p++)
        bRowOff[p] = (uint32_t)((wn * 32 + p * 16 + rowB) * 128);

    float acc[4][4][4];
#pragma unroll
    for (int mi = 0; mi < 4; mi++)
#pragma unroll
        for (int ni = 0; ni < 4; ni++)
#pragma unroll
            for (int q = 0; q < 4; q++) acc[mi][ni][q] = 0.f;

    int C = K >> 6;

    // prologue: load chunks 0, 1 into stages 0, 1
    {
        uint32_t st = sbase;
        tile_cp(Ah, lda, m0, 0, st, tid);
        tile_cp(Bh, ldb, n0, 0, st + B_OFF, tid);
        if (MODE == 0) {
            tile_cp(Al, lda, m0, 0, st + TILE_SZ, tid);
            tile_cp(Bl, ldb, n0, 0, st + B_OFF + TILE_SZ, tid);
        }
        CP_COMMIT();
    }
    if (C > 1) {
        uint32_t st = sbase + STG;
        tile_cp(Ah, lda, m0, 64, st, tid);
        tile_cp(Bh, ldb, n0, 64, st + B_OFF, tid);
        if (MODE == 0) {
            tile_cp(Al, lda, m0, 64, st + TILE_SZ, tid);
            tile_cp(Bl, ldb, n0, 64, st + B_OFF + TILE_SZ, tid);
        }
        CP_COMMIT();
    }

    int stage = 0;       // stage holding chunk c
    for (int c = 0; c < C; c++) {
        if (c + 1 < C) CP_WAIT1(); else CP_WAIT0();
        __syncthreads();   // all warps past compute c-1; chunk c visible to all

        // issue prefetch for chunk c+2 into stage (c+2)%3 (= stage of c-1)
        if (c + 2 < C) {
            int pst = stage + 2; if (pst >= 3) pst -= 3;
            uint32_t stn = sbase + (uint32_t)pst * STG;
            ll k0 = (ll)(c + 2) * 64;
            tile_cp(Ah, lda, m0, k0, stn, tid);
            tile_cp(Bh, ldb, n0, k0, stn + B_OFF, tid);
            if (MODE == 0) {
                tile_cp(Al, lda, m0, k0, stn + TILE_SZ, tid);
                tile_cp(Bl, ldb, n0, k0, stn + B_OFF + TILE_SZ, tid);
            }
            CP_COMMIT();
        }

        uint32_t st = sbase + (uint32_t)stage * STG;
#pragma unroll
        for (int kk = 0; kk < 4; kk++) {
            uint32_t chA = (uint32_t)(((kk * 2 + jA) ^ rl) << 4);
            uint32_t chB = (uint32_t)(((kk * 2 + jB) ^ rl) << 4);
            // pass 1: Ah x Bh
            uint32_t ah[4][4];
#pragma unroll
            for (int mi = 0; mi < 4; mi++)
                ldsm4(st + aRowOff[mi] + chA,
                      ah[mi][0], ah[mi][1], ah[mi][2], ah[mi][3]);
            uint32_t bh[4][2];
#pragma unroll
            for (int p = 0; p < 2; p++) {
                uint32_t r0, r1, r2, r3;
                ldsm4(st + B_OFF + bRowOff[p] + chB, r0, r1, r2, r3);
                bh[2 * p][0] = r0; bh[2 * p][1] = r1;
                bh[2 * p + 1][0] = r2; bh[2 * p + 1][1] = r3;
            }
#pragma unroll
            for (int mi = 0; mi < 4; mi++)
#pragma unroll
                for (int ni = 0; ni < 4; ni++) {
                    if (MODE == 0)
                        hmma_bf16(acc[mi][ni], ah[mi][0], ah[mi][1], ah[mi][2], ah[mi][3],
                                  bh[ni][0], bh[ni][1]);
                    else
                        hmma_fp16(acc[mi][ni], ah[mi][0], ah[mi][1], ah[mi][2], ah[mi][3],
                                  bh[ni][0], bh[ni][1]);
                }
            if (MODE == 0) {
                // pass 2: Ah x Bl
                uint32_t bl[4][2];
#pragma unroll
                for (int p = 0; p < 2; p++) {
                    uint32_t r0, r1, r2, r3;
                    ldsm4(st + B_OFF + TILE_SZ + bRowOff[p] + chB, r0, r1, r2, r3);
                    bl[2 * p][0] = r0; bl[2 * p][1] = r1;
                    bl[2 * p + 1][0] = r2; bl[2 * p + 1][1] = r3;
                }
#pragma unroll
                for (int mi = 0; mi < 4; mi++)
#pragma unroll
                    for (int ni = 0; ni < 4; ni++)
                        hmma_bf16(acc[mi][ni], ah[mi][0], ah[mi][1], ah[mi][2], ah[mi][3],
                                  bl[ni][0], bl[ni][1]);
                // pass 3: Al x Bh
                uint32_t al[4][4];
#pragma unroll
                for (int mi = 0; mi < 4; mi++)
                    ldsm4(st + TILE_SZ + aRowOff[mi] + chA,
                          al[mi][0], al[mi][1], al[mi][2], al[mi][3]);
#pragma unroll
                for (int mi = 0; mi < 4; mi++)
#pragma unroll
                    for (int ni = 0; ni < 4; ni++)
                        hmma_bf16(acc[mi][ni], al[mi][0], al[mi][1], al[mi][2], al[mi][3],
                                  bh[ni][0], bh[ni][1]);
            }
        }

        stage++; if (stage >= 3) stage -= 3;
    }

    // ---- Epilogue: acc -> smem staging -> coalesced global ----
    __syncthreads();   // all warps done reading stage smem before pad reuse
    float* ep = (float*)smem;
    {
        int gr = lane >> 2, gc = lane & 3;
#pragma unroll
        for (int mi = 0; mi < 4; mi++)
#pragma unroll
            for (int ni = 0; ni < 4; ni++) {
                int row = wm * 64 + mi * 16 + gr;
                int col = wn * 32 + ni * 8 + gc * 2;
                *(float2*)&ep[row * EP_PITCH + col] =
                    make_float2(acc[mi][ni][0], acc[mi][ni][1]);
                *(float2*)&ep[(row + 8) * EP_PITCH + col] =
                    make_float2(acc[mi][ni][2], acc[mi][ni][3]);
            }
    }
    __syncthreads();

    {
        int lc = tid & 31;        // col group (x4)
        int rbase = tid >> 5;     // 0..7
        float4 bv = make_float4(0.f, 0.f, 0.f, 0.f);
        if (biasz) bv = *(const float4*)(biasz + n0 + lc * 4);
#pragma unroll
        for (int i = 0; i < 16; i++) {
            int row = rbase + i * 8;
            float4 v = *(float4*)&ep[row * EP_PITCH + lc * 4];
            v.x += bv.x; v.y += bv.y; v.z += bv.z; v.w += bv.w;
            ll off = coff + (ll)row * ldc + lc * 4;
            if (Cf) *(float4*)(Cf + off) = v;
            if (Chi) {
                if (Clo) {
                    // bf16 split output
                    __nv_bfloat16 h0 = __float2bfloat16(v.x);
                    __nv_bfloat16 h1 = __float2bfloat16(v.y);
                    __nv_bfloat16 h2 = __float2bfloat16(v.z);
                    __nv_bfloat16 h3 = __float2bfloat16(v.w);
                    __nv_bfloat16 l0 = __float2bfloat16(v.x - __bfloat162float(h0));
                    __nv_bfloat16 l1 = __float2bfloat16(v.y - __bfloat162float(h1));
                    __nv_bfloat16 l2 = __float2bfloat16(v.z - __bfloat162float(h2));
                    __nv_bfloat16 l3 = __float2bfloat16(v.w - __bfloat162float(h3));
                    uint2 hv, lv;
                    __nv_bfloat16* hp = (__nv_bfloat16*)&hv;
                    __nv_bfloat16* lp = (__nv_bfloat16*)&lv;
                    hp[0] = h0; hp[1] = h1; hp[2] = h2; hp[3] = h3;
                    lp[0] = l0; lp[1] = l1; lp[2] = l2; lp[3] = l3;
                    *(uint2*)(Chi + off) = hv;
                    *(uint2*)(Clo + off) = lv;
                } else {
                    // fp16 single output
                    uint2 hv;
                    __half* hp = (__half*)&hv;
                    hp[0] = __float2half(v.x);
                    hp[1] = __float2half(v.y);
                    hp[2] = __float2half(v.z);
                    hp[3] = __float2half(v.w);
                    *(uint2*)((__half*)Chi + off) = hv;
                }
            }
        }
    }
}

// ---------------------------------------------------------------------------
// Fused BN folding for all three weight sets.
// ---------------------------------------------------------------------------
__global__ void fold_all(const float* __restrict__ W_phi,
                         const float* __restrict__ pg, const float* __restrict__ pb,
                         const float* __restrict__ pm, const float* __restrict__ pv,
                         const float* __restrict__ W_psi,
                         const float* __restrict__ sg, const float* __restrict__ sb,
                         const float* __restrict__ sm, const float* __restrict__ sv,
                         const float* __restrict__ W_red,
                         const float* __restrict__ rg, const float* __restrict__ rb,
                         const float* __restrict__ rm, const float* __restrict__ rv,
                         float* __restrict__ Wphi_f, float* __restrict__ bphi,
                         float* __restrict__ Wpsi_f,
                         __half* __restrict__ Wred_f16, float* __restrict__ bred)
{
    int blk = blockIdx.x;
    int tid = threadIdx.x;
    __shared__ float red[256];
    if (blk < HP) {
        int o = blk;
        float partial = 0.f;
        const float* wrow = W_phi + (ll)o * D_;
        float* wfrow = Wphi_f + (ll)o * D_;
        for (int d = tid; d < D_; d += 256) {
            float sc = pg[d] * rsqrtf(pv[d] + 1e-5f);
            float sh = pb[d] - pm[d] * sc;
            float w = wrow[d];
            wfrow[d] = w * sc;
            partial += w * sh;
        }
        red[tid] = partial;
        __syncthreads();
        for (int s = 128; s > 0; s >>= 1) {
            if (tid < s) red[tid] += red[tid + s];
            __syncthreads();
        }
        if (tid == 0) bphi[o] = red[0];
    } else if (blk < HP + PROJ) {
        int o = blk - HP;
        const float* wrow = W_psi + (ll)o * D_;
        float* wfrow = Wpsi_f + (ll)o * D_;
        for (int d = tid; d < D_; d += 256) {
            float sc = sg[d] * rsqrtf(sv[d] + 1e-5f);
            wfrow[d] = wrow[d] * sc;
        }
    } else {
        int o = blk - HP - PROJ;
        float partial = 0.f;
        const float* wrow = W_red + (ll)o * HD;
        __half* wfr = Wred_f16 + (ll)o * HD;
        for (int d = tid; d < HD; d += 256) {
            float sc = rg[d] * rsqrtf(rv[d] + 1e-5f);
            float sh = rb[d] - rm[d] * sc;
            float w = wrow[d];
            wfr[d] = __float2half(w * sc);
            partial += w * sh;
        }
        red[tid] = partial;
        __syncthreads();
        for (int s = 128; s > 0; s >>= 1) {
            if (tid < s) red[tid] += red[tid + s];
            __syncthreads();
        }
        if (tid == 0) bred[o] = red[0];
    }
}

// ---------------------------------------------------------------------------
// Fused transpose of both folded weights: fp32 [R,C] -> split bf16 [C,R].
// ---------------------------------------------------------------------------
__global__ void __launch_bounds__(256)
transpose_both(const float* __restrict__ wphi, __nv_bfloat16* __restrict__ phi_hi,
               __nv_bfloat16* __restrict__ phi_lo,
               const float* __restrict__ wpsi, __nv_bfloat16* __restrict__ psi_hi,
               __nv_bfloat16* __restrict__ psi_lo)
{
    __shared__ float t[32][33];
    const float* in;
    __nv_bfloat16 *ohi, *olo;
    int R, r0;
    if (blockIdx.x < HP / 32) {
        in = wphi; ohi = phi_hi; olo = phi_lo; R = HP; r0 = blockIdx.x * 32;
    } else {
        in = wpsi; ohi = psi_hi; olo = psi_lo; R = PROJ;
        r0 = (blockIdx.x - HP / 32) * 32;
    }
    int c0 = blockIdx.y * 32;
#pragma unroll
    for (int j = 0; j < 4; j++) {
        int r = threadIdx.y + j * 8;
        t[r][threadIdx.x] = in[(ll)(r0 + r) * D_ + c0 + threadIdx.x];
    }
    __syncthreads();
#pragma unroll
    for (int j = 0; j < 4; j++) {
        int c = threadIdx.y + j * 8;
        float v = t[threadIdx.x][c];
        __nv_bfloat16 hi = __float2bfloat16(v);
        ll off = (ll)(c0 + c) * R + r0 + threadIdx.x;
        ohi[off] = hi;
        olo[off] = __float2bfloat16(v - __bfloat162float(hi));
    }
}

// ---------------------------------------------------------------------------
// u[g][d] = sum_p bphi[g*PROJ+p] * Wpsi_f[p][d]
// ---------------------------------------------------------------------------
__global__ void __launch_bounds__(512)
u_kernel(const float* __restrict__ bphi, const float* __restrict__ wpsi,
         float* __restrict__ u)
{
    int g = blockIdx.x;
    int d = threadIdx.x;
    float acc = 0.f;
    const float* bp = bphi + g * PROJ;
    for (int p = 0; p < PROJ; p++)
        acc += bp[p] * wpsi[(ll)p * D_ + d];
    u[g * D_ + d] = acc;
}

// ---------------------------------------------------------------------------
// cb[g][b*TK+k] = sum_d h[b][k][d] * u[g][d].  One warp per (b,k) row.
// ---------------------------------------------------------------------------
__global__ void __launch_bounds__(256)
colbias_kernel(const float* __restrict__ h, const float* __restrict__ u,
               float* __restrict__ cb)
{
    __shared__ float us[NH * D_];
    int tid = threadIdx.x;
    for (int i = tid; i < NH * D_; i += 256) us[i] = u[i];
    __syncthreads();
    int w = tid >> 5, l = tid & 31;
    ll r = (ll)blockIdx.x * 8 + w;          // (b,k) row in [0, B_*TK)
    const float* row = h + r * D_;
    float a0 = 0.f, a1 = 0.f, a2 = 0.f, a3 = 0.f;
    for (int i = l; i < D_; i += 32) {
        float v = row[i];
        a0 += v * us[i];
        a1 += v * us[D_ + i];
        a2 += v * us[2 * D_ + i];
        a3 += v * us[3 * D_ + i];
    }
#pragma unroll
    for (int s = 16; s > 0; s >>= 1) {
        a0 += __shfl_xor_sync(0xFFFFFFFF, a0, s);
        a1 += __shfl_xor_sync(0xFFFFFFFF, a1, s);
        a2 += __shfl_xor_sync(0xFFFFFFFF, a2, s);
        a3 += __shfl_xor_sync(0xFFFFFFFF, a3, s);
    }
    if (l == 0) {
        const ll BT = (ll)B_ * TK;
        cb[r] = a0;
        cb[BT + r] = a1;
        cb[2 * BT + r] = a2;
        cb[3 * BT + r] = a3;
    }
}

// ---------------------------------------------------------------------------
// Elementwise fp32 -> bf16 hi/lo split (for s)
// ---------------------------------------------------------------------------
__global__ void __launch_bounds__(256)
split_kernel(const float* __restrict__ x, __nv_bfloat16* __restrict__ hi,
             __nv_bfloat16* __restrict__ lo, ll n4)
{
    ll i = (ll)blockIdx.x * 256 + threadIdx.x;
    if (i >= n4) return;
    float4 v = *(const float4*)(x + i * 4);
    __nv_bfloat16 h0 = __float2bfloat16(v.x);
    __nv_bfloat16 h1 = __float2bfloat16(v.y);
    __nv_bfloat16 h2 = __float2bfloat16(v.z);
    __nv_bfloat16 h3 = __float2bfloat16(v.w);
    uint2 hv, lv;
    __nv_bfloat16* hp = (__nv_bfloat16*)&hv;
    __nv_bfloat16* lp = (__nv_bfloat16*)&lv;
    hp[0] = h0; hp[1] = h1; hp[2] = h2; hp[3] = h3;
    lp[0] = __float2bfloat16(v.x - __bfloat162float(h0));
    lp[1] = __float2bfloat16(v.y - __bfloat162float(h1));
    lp[2] = __float2bfloat16(v.z - __bfloat162float(h2));
    lp[3] = __float2bfloat16(v.w - __bfloat162float(h3));
    *(uint2*)(hi + i * 4) = hv;
    *(uint2*)(lo + i * 4) = lv;
}

// ---------------------------------------------------------------------------
// Fused h prep, vectorized: one read of h produces h_hi/h_lo (row-major,
// uint2 stores) AND ht fp16 (transposed [b][d][k], uint2 stores).
// ---------------------------------------------------------------------------
__global__ void __launch_bounds__(256)
prep_h(const float* __restrict__ h, __nv_bfloat16* __restrict__ hhi,
       __nv_bfloat16* __restrict__ hlo, __half* __restrict__ tf)
{
    __shared__ float t[32][33];
    int b = blockIdx.z;
    int k0 = blockIdx.x * 32;
    int d0 = blockIdx.y * 32;
    int tx = threadIdx.x;     // 0..7  (d quad)
    int ty = threadIdx.y;     // 0..31 (k)
    const float* hb = h + (ll)b * TK * D_;

    float4 v = *(const float4*)(hb + (ll)(k0 + ty) * D_ + d0 + tx * 4);
    t[ty][tx * 4 + 0] = v.x;
    t[ty][tx * 4 + 1] = v.y;
    t[ty][tx * 4 + 2] = v.z;
    t[ty][tx * 4 + 3] = v.w;

    {
        __nv_bfloat16 h0 = __float2bfloat16(v.x);
        __nv_bfloat16 h1 = __float2bfloat16(v.y);
        __nv_bfloat16 h2 = __float2bfloat16(v.z);
        __nv_bfloat16 h3 = __float2bfloat16(v.w);
        uint2 hv, lv;
        __nv_bfloat16* hp = (__nv_bfloat16*)&hv;
        __nv_bfloat16* lp = (__nv_bfloat16*)&lv;
        hp[0] = h0; hp[1] = h1; hp[2] = h2; hp[3] = h3;
        lp[0] = __float2bfloat16(v.x - __bfloat162float(h0));
        lp[1] = __float2bfloat16(v.y - __bfloat162float(h1));
        lp[2] = __float2bfloat16(v.z - __bfloat162float(h2));
        lp[3] = __float2bfloat16(v.w - __bfloat162float(h3));
        ll off = (ll)b * TK * D_ + (ll)(k0 + ty) * D_ + d0 + tx * 4;
        *(uint2*)(hhi + off) = hv;
        *(uint2*)(hlo + off) = lv;
    }
    __syncthreads();

    {
        float a0 = t[tx * 4 + 0][ty];
        float a1 = t[tx * 4 + 1][ty];
        float a2 = t[tx * 4 + 2][ty];
        float a3 = t[tx * 4 + 3][ty];
        __half2 p01 = __floats2half2_rn(a0, a1);
        __half2 p23 = __floats2half2_rn(a2, a3);
        uint2 hv;
        hv.x = *(uint32_t*)&p01;
        hv.y = *(uint32_t*)&p23;
        *(uint2*)(tf + (ll)b * D_ * TK + (ll)(d0 + ty) * TK + k0 + tx * 4) = hv;
    }
}

// ---------------------------------------------------------------------------
// Row softmax, in place, + fp16 copy. Warp-per-row, 8 rows per 256-thread
// block, zero block barriers, MLP=8 float4 loads per thread.
// ---------------------------------------------------------------------------
__global__ void __launch_bounds__(256)
softmax_kernel(float* __restrict__ a, __half* __restrict__ af16)
{
    int w = threadIdx.x >> 5, lane = threadIdx.x & 31;
    ll row = (ll)blockIdx.x * 8 + w;
    float* rp = a + row * TK;

    float4 x[8];
#pragma unroll
    for (int i = 0; i < 8; i++)
        x[i] = *(float4*)(rp + i * 128 + lane * 4);

    float m = -INFINITY;
#pragma unroll
    for (int i = 0; i < 8; i++)
        m = fmaxf(m, fmaxf(fmaxf(x[i].x, x[i].y), fmaxf(x[i].z, x[i].w)));
#pragma unroll
    for (int s = 16; s > 0; s >>= 1)
        m = fmaxf(m, __shfl_xor_sync(0xFFFFFFFF, m, s));

    float sum = 0.f;
#pragma unroll
    for (int i = 0; i < 8; i++) {
        x[i].x = __expf(x[i].x - m);
        x[i].y = __expf(x[i].y - m);
        x[i].z = __expf(x[i].z - m);
        x[i].w = __expf(x[i].w - m);
        sum += (x[i].x + x[i].y) + (x[i].z + x[i].w);
    }
#pragma unroll
    for (int s = 16; s > 0; s >>= 1)
        sum += __shfl_xor_sync(0xFFFFFFFF, sum, s);
    float inv = 1.f / sum;

    __half* fp = af16 + row * TK;
#pragma unroll
    for (int i = 0; i < 8; i++) {
        float4 o = make_float4(x[i].x * inv, x[i].y * inv,
                               x[i].z * inv, x[i].w * inv);
        *(float4*)(rp + i * 128 + lane * 4) = o;
        __half2 h01 = __floats2half2_rn(o.x, o.y);
        __half2 h23 = __floats2half2_rn(o.z, o.w);
        uint2 hv;
        hv.x = *(uint32_t*)&h01;
        hv.y = *(uint32_t*)&h23;
        *(uint2*)(fp + i * 128 + lane * 4) = hv;
    }
}

// ---------------------------------------------------------------------------
extern "C" void kernel_launch(void* const* d_in, const int* in_sizes, int n_in,
                              void* d_out, int out_size)
{
    const float* s_in      = (const float*)d_in[0];
    const float* h_in      = (const float*)d_in[1];
    const float* phi_gamma = (const float*)d_in[2];
    const float* phi_beta  = (const float*)d_in[3];
    const float* phi_mean  = (const float*)d_in[4];
    const float* phi_var   = (const float*)d_in[5];
    const float* W_phi     = (const float*)d_in[6];
    const float* psi_gamma = (const float*)d_in[7];
    const float* psi_beta  = (const float*)d_in[8];
    const float* psi_mean  = (const float*)d_in[9];
    const float* psi_var   = (const float*)d_in[10];
    const float* W_psi     = (const float*)d_in[11];
    const float* red_gamma = (const float*)d_in[12];
    const float* red_beta  = (const float*)d_in[13];
    const float* red_mean  = (const float*)d_in[14];
    const float* red_var   = (const float*)d_in[15];
    const float* W_red     = (const float*)d_in[16];

    float* a_out = (float*)d_out;               // [H, B, Tq, Tk]
    float* c_out = a_out + A_ELEMS;             // [B, Tq, D]

    __nv_bfloat16 *s_hi, *s_lo, *h_hi, *h_lo;
    __nv_bfloat16 *ms_hi, *ms_lo;
    __nv_bfloat16 *WphiT_hi, *WphiT_lo, *WpsiT_hi, *WpsiT_lo, *Gt_hi, *Gt_lo;
    __half *ht_f16, *a_f16, *ctx_f16, *Wred_f16;
    float *bphi, *bred, *Wphi_f, *Wpsi_f, *u_dev, *cb;
    cudaGetSymbolAddress((void**)&s_hi, g_s_hi);   cudaGetSymbolAddress((void**)&s_lo, g_s_lo);
    cudaGetSymbolAddress((void**)&h_hi, g_h_hi);   cudaGetSymbolAddress((void**)&h_lo, g_h_lo);
    cudaGetSymbolAddress((void**)&ht_f16, g_ht_f16);
    cudaGetSymbolAddress((void**)&ms_hi, g_ms_hi); cudaGetSymbolAddress((void**)&ms_lo, g_ms_lo);
    cudaGetSymbolAddress((void**)&a_f16, g_a_f16);
    cudaGetSymbolAddress((void**)&ctx_f16, g_ctx_f16);
    cudaGetSymbolAddress((void**)&Wred_f16, g_Wred_f16);
    cudaGetSymbolAddress((void**)&WphiT_hi, g_WphiT_hi); cudaGetSymbolAddress((void**)&WphiT_lo, g_WphiT_lo);
    cudaGetSymbolAddress((void**)&WpsiT_hi, g_WpsiT_hi); cudaGetSymbolAddress((void**)&WpsiT_lo, g_WpsiT_lo);
    cudaGetSymbolAddress((void**)&Gt_hi, g_Gt_hi); cudaGetSymbolAddress((void**)&Gt_lo, g_Gt_lo);
    cudaGetSymbolAddress((void**)&Wphi_f, g_Wphi_f); cudaGetSymbolAddress((void**)&Wpsi_f, g_Wpsi_f);
    cudaGetSymbolAddress((void**)&u_dev, g_u); cudaGetSymbolAddress((void**)&cb, g_cb);
    cudaGetSymbolAddress((void**)&bphi, g_bphi);
    cudaGetSymbolAddress((void**)&bred, g_bred);

    cudaFuncSetAttribute(gemm_tc<0>, cudaFuncAttributeMaxDynamicSharedMemorySize,
                         SMEM_MODE0);
    cudaFuncSetAttribute(gemm_tc<1>, cudaFuncAttributeMaxDynamicSharedMemorySize,
                         SMEM_MODE1);

    // ---- streams & events: prep-phase fork only (falls back to serial) ----
    cudaStream_t sA = 0;
    if (cudaStreamCreateWithFlags(&sA, cudaStreamNonBlocking) != cudaSuccess) sA = 0;
    cudaEvent_t evF, evSplit, evFold, evPrep;
    cudaEventCreateWithFlags(&evF,     cudaEventDisableTiming);
    cudaEventCreateWithFlags(&evSplit, cudaEventDisableTiming);
    cudaEventCreateWithFlags(&evFold,  cudaEventDisableTiming);
    cudaEventCreateWithFlags(&evPrep,  cudaEventDisableTiming);

    // fork
    cudaEventRecord(evF, 0);
    cudaStreamWaitEvent(sA, evF, 0);

    // ---- side stream: input conversions + bias pipeline ----
    split_kernel<<<(int)(((ll)B_ * TQ * D_ / 4 + 255) / 256), 256, 0, sA>>>(
        s_in, s_hi, s_lo, (ll)B_ * TQ * D_ / 4);
    cudaEventRecord(evSplit, sA);
    prep_h<<<dim3(TK / 32, D_ / 32, B_), dim3(8, 32), 0, sA>>>(h_in, h_hi, h_lo, ht_f16);

    // ---- main stream: weight pipeline ----
    fold_all<<<HP + PROJ + D_, 256, 0, 0>>>(
        W_phi, phi_gamma, phi_beta, phi_mean, phi_var,
        W_psi, psi_gamma, psi_beta, psi_mean, psi_var,
        W_red, red_gamma, red_beta, red_mean, red_var,
        Wphi_f, bphi, Wpsi_f, Wred_f16, bred);
    cudaEventRecord(evFold, 0);
    transpose_both<<<dim3((HP + PROJ) / 32, D_ / 32), dim3(32, 8), 0, 0>>>(
        Wphi_f, WphiT_hi, WphiT_lo, Wpsi_f, WpsiT_hi, WpsiT_lo);

    // side: u & colbias need fold_all's bphi/Wpsi_f
    cudaStreamWaitEvent(sA, evFold, 0);
    u_kernel<<<NH, 512, 0, sA>>>(bphi, Wpsi_f, u_dev);
    colbias_kernel<<<(int)((ll)B_ * TK / 8), 256, 0, sA>>>(h_in, u_dev, cb);
    cudaEventRecord(evPrep, sA);

    // main: Gt GEMM
    gemm_tc<0><<<dim3(4, 4, NH), 256, SMEM_MODE0, 0>>>(
        WpsiT_hi, WpsiT_lo, WphiT_hi, WphiT_lo, nullptr,
        nullptr, Gt_hi, Gt_lo,
        PROJ, PROJ, HP, D_,
        1, 0, 0, (ll)PROJ, 0, (ll)D_ * D_, 0, 0, 0);

    // ---- join: everything below is serial on the main stream ----
    cudaStreamWaitEvent(0, evSplit, 0);
    // 5. sG = s @ Gt^T : [8192, 2048], K=512 -> split out (ms buffers)
    gemm_tc<0><<<dim3(HP / 128, (B_ * TQ) / 128, 1), 256, SMEM_MODE0, 0>>>(
        s_hi, s_lo, Gt_hi, Gt_lo, nullptr,
        nullptr, ms_hi, ms_lo,
        D_, D_, D_, HP,
        1, 0, 0, 0, 0, 0, 0, 0, 0);

    cudaStreamWaitEvent(0, evPrep, 0);
    // 6. logits e[g,b,q,k] = sG_g[b,q,:] . h[b,k,:] + cb[g,b,k] -> fp32 a_out
    gemm_tc<0><<<dim3(TK / 128, TQ / 128, B_ * NH), 256, SMEM_MODE0, 0>>>(
        ms_hi, ms_lo, h_hi, h_lo, cb,
        a_out, nullptr, nullptr,
        D_, HP, D_, TK,
        NH,
        (ll)TQ * HP, (ll)PROJ,
        (ll)TK * D_, 0,
        (ll)TQ * TK, (ll)B_ * TQ * TK,
        (ll)TK, (ll)B_ * TK);

    // 7. softmax (in place) + fp16 copy — warp-per-row, 8 rows/block
    softmax_kernel<<<NH * B_ * TQ / 8, 256, 0, 0>>>(a_out, a_f16);

    // 8. ctx[b,q,g*D+d] = a[g,b,q,:] . ht[b,d,:]  (fp16 1-pass) -> fp16 single out
    gemm_tc<1><<<dim3(D_ / 128, TQ / 128, B_ * NH), 256, SMEM_MODE1, 0>>>(
        (const __nv_bfloat16*)a_f16, nullptr,
        (const __nv_bfloat16*)ht_f16, nullptr, nullptr,
        nullptr, (__nv_bfloat16*)ctx_f16, nullptr,
        TK, TK, TK, HD,
        NH,
        (ll)TQ * TK, (ll)B_ * TQ * TK,
        (ll)D_ * TK, 0,
        (ll)TQ * HD, (ll)D_,
        0, 0);

    // 9. c = ctx @ Wred^T + bred : [8192, 512], K=2048 (fp16 1-pass) -> fp32 out
    gemm_tc<1><<<dim3(D_ / 128, (B_ * TQ) / 128, 1), 256, SMEM_MODE1, 0>>>(
        (const __nv_bfloat16*)ctx_f16, nullptr,
        (const __nv_bfloat16*)Wred_f16, nullptr, bred,
        c_out, nullptr, nullptr,
        HD, HD, HD, D_,
        1, 0, 0, 0, 0, 0, 0, 0, 0);
    // (streams/events intentionally not destroyed; kernel_launch is called
    //  only a handful of times outside the timed graph replay)
}

// round 16
// speedup vs baseline: 1.4819x; 1.0061x over previous
#include <cuda_runtime.h>
#include <cuda_bf16.h>
#include <cuda_fp16.h>
#include <math.h>
#include <stdint.h>

// Problem constants
#define B_   32
#define TQ   256
#define TK   1024
#define D_   512
#define NH   4
#define PROJ 512
#define HP   (NH * PROJ)      // 2048
#define HD   (NH * D_)        // 2048
#define A_ELEMS (4LL * 32 * 256 * 1024)   // 33554432

typedef long long ll;

// ---------------------------------------------------------------------------
// Scratch (static device arrays — sanctioned workaround for no-alloc rule)
// ---------------------------------------------------------------------------
__device__ __align__(128) __nv_bfloat16 g_s_hi[(size_t)B_ * TQ * D_];
__device__ __align__(128) __nv_bfloat16 g_s_lo[(size_t)B_ * TQ * D_];
__device__ __align__(128) __nv_bfloat16 g_h_hi[(size_t)B_ * TK * D_];
__device__ __align__(128) __nv_bfloat16 g_h_lo[(size_t)B_ * TK * D_];
__device__ __align__(128) __half        g_ht_f16[(size_t)B_ * D_ * TK];
__device__ __align__(128) __nv_bfloat16 g_ms_hi[(size_t)B_ * TQ * HP];   // sG
__device__ __align__(128) __nv_bfloat16 g_ms_lo[(size_t)B_ * TQ * HP];
__device__ __align__(128) __half        g_a_f16[(size_t)A_ELEMS];
__device__ __align__(128) __half        g_ctx_f16[(size_t)B_ * TQ * HD];
__device__ __align__(128) __half        g_Wred_f16[(size_t)D_ * HD];
// G-decomposition scratch
__device__ __align__(128) float         g_Wphi_f[(size_t)HP * D_];
__device__ __align__(128) float         g_Wpsi_f[(size_t)PROJ * D_];
__device__ __align__(128) __nv_bfloat16 g_WphiT_hi[(size_t)D_ * HP];
__device__ __align__(128) __nv_bfloat16 g_WphiT_lo[(size_t)D_ * HP];
__device__ __align__(128) __nv_bfloat16 g_WpsiT_hi[(size_t)D_ * PROJ];
__device__ __align__(128) __nv_bfloat16 g_WpsiT_lo[(size_t)D_ * PROJ];
__device__ __align__(128) __nv_bfloat16 g_Gt_hi[(size_t)NH * D_ * D_];
__device__ __align__(128) __nv_bfloat16 g_Gt_lo[(size_t)NH * D_ * D_];
__device__ __align__(128) float         g_u[(size_t)NH * D_];
__device__ __align__(128) float         g_cb[(size_t)NH * B_ * TK];
__device__ float g_bphi[HP];
__device__ float g_bred[D_];

// ---------------------------------------------------------------------------
// Helpers
// ---------------------------------------------------------------------------
__device__ __forceinline__ uint32_t smem_to_u32(const void* p) {
    uint32_t a;
    asm("{ .reg .u64 t; cvta.to.shared.u64 t, %1; cvt.u32.u64 %0, t; }"
        : "=r"(a) : "l"(p));
    return a;
}

__device__ __forceinline__ void ldsm4(uint32_t addr, uint32_t& r0, uint32_t& r1,
                                      uint32_t& r2, uint32_t& r3)
{
    asm volatile("ldmatrix.sync.aligned.m8n8.x4.shared.b16 {%0,%1,%2,%3}, [%4];"
                 : "=r"(r0), "=r"(r1), "=r"(r2), "=r"(r3) : "r"(addr));
}

__device__ __forceinline__ void hmma_bf16(float* c, uint32_t a0, uint32_t a1,
                                          uint32_t a2, uint32_t a3,
                                          uint32_t b0, uint32_t b1)
{
    asm volatile(
        "mma.sync.aligned.m16n8k16.row.col.f32.bf16.bf16.f32 "
        "{%0,%1,%2,%3}, {%4,%5,%6,%7}, {%8,%9}, {%0,%1,%2,%3};"
        : "+f"(c[0]), "+f"(c[1]), "+f"(c[2]), "+f"(c[3])
        : "r"(a0), "r"(a1), "r"(a2), "r"(a3), "r"(b0), "r"(b1));
}

__device__ __forceinline__ void hmma_fp16(float* c, uint32_t a0, uint32_t a1,
                                          uint32_t a2, uint32_t a3,
                                          uint32_t b0, uint32_t b1)
{
    asm volatile(
        "mma.sync.aligned.m16n8k16.row.col.f32.f16.f16.f32 "
        "{%0,%1,%2,%3}, {%4,%5,%6,%7}, {%8,%9}, {%0,%1,%2,%3};"
        : "+f"(c[0]), "+f"(c[1]), "+f"(c[2]), "+f"(c[3])
        : "r"(a0), "r"(a1), "r"(a2), "r"(a3), "r"(b0), "r"(b1));
}

// streaming (evict-first) fp32 float4 load/store for read-once / write-only data
__device__ __forceinline__ float4 ldg_cs4(const float* p) {
    float4 v;
    asm volatile("ld.global.cs.v4.f32 {%0,%1,%2,%3}, [%4];"
                 : "=f"(v.x), "=f"(v.y), "=f"(v.z), "=f"(v.w) : "l"(p));
    return v;
}
__device__ __forceinline__ void stg_cs4(float* p, float4 v) {
    asm volatile("st.global.cs.v4.f32 [%0], {%1,%2,%3,%4};"
                 :: "l"(p), "f"(v.x), "f"(v.y), "f"(v.z), "f"(v.w) : "memory");
}

#define CP_ASYNC16(sa, ga) \
    asm volatile("cp.async.cg.shared.global [%0], [%1], 16;" :: "r"(sa), "l"(ga))
#define CP_COMMIT() asm volatile("cp.async.commit_group;" ::: "memory")
#define CP_WAIT1()  asm volatile("cp.async.wait_group 1;" ::: "memory")
#define CP_WAIT0()  asm volatile("cp.async.wait_group 0;" ::: "memory")

// ---------------------------------------------------------------------------
// smem: 3-stage ring.
// MODE 0 (3-pass bf16 pairs): 3 stages x {Ahi,Alo,Bhi,Blo} = 192 KB
// MODE 1 (1-pass fp16):       3 stages x {A,B} = 96 KB
// ---------------------------------------------------------------------------
#define TILE_SZ 16384
#define EP_PITCH 132
#define SMEM_MODE0 (12 * TILE_SZ)          // 196608
#define SMEM_MODE1 (6 * TILE_SZ)           // 98304 (>= 67584 epilogue pad)

// Load one 128x64 bf16/fp16 tile (rows row0.., cols k0..k0+63) into swizzled smem.
__device__ __forceinline__ void tile_cp(const __nv_bfloat16* __restrict__ g,
                                        ll stride, ll row0, ll k0,
                                        uint32_t stile, int tid)
{
    int c = tid & 7;           // 16B chunk within row
    int r0 = tid >> 3;         // 0..31
    const char* gp = (const char*)(g + row0 * stride + k0 + c * 8);
    ll rb = stride * 2;
#pragma unroll
    for (int i = 0; i < 4; i++) {
        int r = r0 + i * 32;
        uint32_t sa = stile + (uint32_t)(r * 128) + (uint32_t)((c ^ (r & 7)) << 4);
        CP_ASYNC16(sa, gp + (ll)r * rb);
    }
}

// ---------------------------------------------------------------------------
// Tensor-core GEMM: C[M,N] = A[M,K] @ B[N,K]^T (+per-column bias)
// MODE 0: split-bf16 3-pass (AhBh + AhBl + AlBh), fp32 accumulate.
// MODE 1: single-pass fp16 (Ahi/Bhi carry fp16 bits; Alo/Blo ignored).
// 3-stage cp.async ring, ONE barrier per K-chunk (prefetch issued pre-compute).
// Outputs: Cf (fp32); Chi+Clo (bf16 split); Chi alone (fp16 single).
// Batched via blockIdx.z (z1 = z/zdiv, z2 = z%zdiv); bias has z-strides too.
// ---------------------------------------------------------------------------
template <int MODE>
__global__ void __launch_bounds__(256)
gemm_tc(const __nv_bfloat16* __restrict__ Ahi, const __nv_bfloat16* __restrict__ Alo,
        const __nv_bfloat16* __restrict__ Bhi, const __nv_bfloat16* __restrict__ Blo,
        const float* __restrict__ bias,
        float* __restrict__ Cf, __nv_bfloat16* __restrict__ Chi, __nv_bfloat16* __restrict__ Clo,
        int K, ll lda, ll ldb, ll ldc,
        int zdiv, ll a_s1, ll a_s2, ll b_s1, ll b_s2, ll c_s1, ll c_s2,
        ll bias_s1, ll bias_s2)
{
    extern __shared__ char smem[];
    uint32_t sbase = smem_to_u32(smem);
    int tid = threadIdx.x;
    int lane = tid & 31;
    int wid = tid >> 5;
    int wm = wid & 1;          // M half (64 rows)
    int wn = wid >> 1;         // N quarter (32 cols)

    constexpr uint32_t NT_TILES = (MODE == 0) ? 4u : 2u;
    constexpr uint32_t STG = NT_TILES * TILE_SZ;
    constexpr uint32_t B_OFF = (MODE == 0) ? 2u * TILE_SZ : TILE_SZ;

    int z = blockIdx.z;
    int z1 = z / zdiv, z2 = z - z1 * zdiv;
    const __nv_bfloat16* Ah = Ahi + z1 * a_s1 + z2 * a_s2;
    const __nv_bfloat16* Al = (MODE == 0) ? Alo + z1 * a_s1 + z2 * a_s2 : nullptr;
    const __nv_bfloat16* Bh = Bhi + z1 * b_s1 + z2 * b_s2;
    const __nv_bfloat16* Bl = (MODE == 0) ? Blo + z1 * b_s1 + z2 * b_s2 : nullptr;
    const float* biasz = bias ? bias + z1 * bias_s1 + z2 * bias_s2 : nullptr;
    ll m0 = (ll)blockIdx.y * 128;
    ll n0 = (ll)blockIdx.x * 128;
    ll coff = z1 * c_s1 + z2 * c_s2 + m0 * ldc + n0;

    // ldmatrix lane geometry
    int rl = lane & 7;
    int sub = lane >> 3;
    int rowA = (sub & 1) * 8 + rl;   // row within 16-row m-tile
    int jA = sub >> 1;               // k-chunk select (0/1)
    int rowB = (sub >> 1) * 8 + rl;  // row within 16-row n-pair
    int jB = sub & 1;

    uint32_t aRowOff[4], bRowOff[2];
#pragma unroll
    for (int mi = 0; mi < 4; mi++)
        aRowOff[mi] = (uint32_t)((wm * 64 + mi * 16 + rowA) * 128);
#pragma unroll
    for (int p = 0; p < 2; p++)
        bRowOff[p] = (uint32_t)((wn * 32 + p * 16 + rowB) * 128);

    float acc[4][4][4];
#pragma unroll
    for (int mi = 0; mi < 4; mi++)
#pragma unroll
        for (int ni = 0; ni < 4; ni++)
#pragma unroll
            for (int q = 0; q < 4; q++) acc[mi][ni][q] = 0.f;

    int C = K >> 6;

    // prologue: load chunks 0, 1 into stages 0, 1
    {
        uint32_t st = sbase;
        tile_cp(Ah, lda, m0, 0, st, tid);
        tile_cp(Bh, ldb, n0, 0, st + B_OFF, tid);
        if (MODE == 0) {
            tile_cp(Al, lda, m0, 0, st + TILE_SZ, tid);
            tile_cp(Bl, ldb, n0, 0, st + B_OFF + TILE_SZ, tid);
        }
        CP_COMMIT();
    }
    if (C > 1) {
        uint32_t st = sbase + STG;
        tile_cp(Ah, lda, m0, 64, st, tid);
        tile_cp(Bh, ldb, n0, 64, st + B_OFF, tid);
        if (MODE == 0) {
            tile_cp(Al, lda, m0, 64, st + TILE_SZ, tid);
            tile_cp(Bl, ldb, n0, 64, st + B_OFF + TILE_SZ, tid);
        }
        CP_COMMIT();
    }

    int stage = 0;       // stage holding chunk c
    for (int c = 0; c < C; c++) {
        if (c + 1 < C) CP_WAIT1(); else CP_WAIT0();
        __syncthreads();   // all warps past compute c-1; chunk c visible to all

        // issue prefetch for chunk c+2 into stage (c+2)%3 (= stage of c-1)
        if (c + 2 < C) {
            int pst = stage + 2; if (pst >= 3) pst -= 3;
            uint32_t stn = sbase + (uint32_t)pst * STG;
            ll k0 = (ll)(c + 2) * 64;
            tile_cp(Ah, lda, m0, k0, stn, tid);
            tile_cp(Bh, ldb, n0, k0, stn + B_OFF, tid);
            if (MODE == 0) {
                tile_cp(Al, lda, m0, k0, stn + TILE_SZ, tid);
                tile_cp(Bl, ldb, n0, k0, stn + B_OFF + TILE_SZ, tid);
            }
            CP_COMMIT();
        }

        uint32_t st = sbase + (uint32_t)stage * STG;
#pragma unroll
        for (int kk = 0; kk < 4; kk++) {
            uint32_t chA = (uint32_t)(((kk * 2 + jA) ^ rl) << 4);
            uint32_t chB = (uint32_t)(((kk * 2 + jB) ^ rl) << 4);
            // pass 1: Ah x Bh
            uint32_t ah[4][4];
#pragma unroll
            for (int mi = 0; mi < 4; mi++)
                ldsm4(st + aRowOff[mi] + chA,
                      ah[mi][0], ah[mi][1], ah[mi][2], ah[mi][3]);
            uint32_t bh[4][2];
#pragma unroll
            for (int p = 0; p < 2; p++) {
                uint32_t r0, r1, r2, r3;
                ldsm4(st + B_OFF + bRowOff[p] + chB, r0, r1, r2, r3);
                bh[2 * p][0] = r0; bh[2 * p][1] = r1;
                bh[2 * p + 1][0] = r2; bh[2 * p + 1][1] = r3;
            }
#pragma unroll
            for (int mi = 0; mi < 4; mi++)
#pragma unroll
                for (int ni = 0; ni < 4; ni++) {
                    if (MODE == 0)
                        hmma_bf16(acc[mi][ni], ah[mi][0], ah[mi][1], ah[mi][2], ah[mi][3],
                                  bh[ni][0], bh[ni][1]);
                    else
                        hmma_fp16(acc[mi][ni], ah[mi][0], ah[mi][1], ah[mi][2], ah[mi][3],
                                  bh[ni][0], bh[ni][1]);
                }
            if (MODE == 0) {
                // pass 2: Ah x Bl
                uint32_t bl[4][2];
#pragma unroll
                for (int p = 0; p < 2; p++) {
                    uint32_t r0, r1, r2, r3;
                    ldsm4(st + B_OFF + TILE_SZ + bRowOff[p] + chB, r0, r1, r2, r3);
                    bl[2 * p][0] = r0; bl[2 * p][1] = r1;
                    bl[2 * p + 1][0] = r2; bl[2 * p + 1][1] = r3;
                }
#pragma unroll
                for (int mi = 0; mi < 4; mi++)
#pragma unroll
                    for (int ni = 0; ni < 4; ni++)
                        hmma_bf16(acc[mi][ni], ah[mi][0], ah[mi][1], ah[mi][2], ah[mi][3],
                                  bl[ni][0], bl[ni][1]);
                // pass 3: Al x Bh
                uint32_t al[4][4];
#pragma unroll
                for (int mi = 0; mi < 4; mi++)
                    ldsm4(st + TILE_SZ + aRowOff[mi] + chA,
                          al[mi][0], al[mi][1], al[mi][2], al[mi][3]);
#pragma unroll
                for (int mi = 0; mi < 4; mi++)
#pragma unroll
                    for (int ni = 0; ni < 4; ni++)
                        hmma_bf16(acc[mi][ni], al[mi][0], al[mi][1], al[mi][2], al[mi][3],
                                  bh[ni][0], bh[ni][1]);
            }
        }

        stage++; if (stage >= 3) stage -= 3;
    }

    // ---- Epilogue: acc -> smem staging -> coalesced global ----
    __syncthreads();   // all warps done reading stage smem before pad reuse
    float* ep = (float*)smem;
    {
        int gr = lane >> 2, gc = lane & 3;
#pragma unroll
        for (int mi = 0; mi < 4; mi++)
#pragma unroll
            for (int ni = 0; ni < 4; ni++) {
                int row = wm * 64 + mi * 16 + gr;
                int col = wn * 32 + ni * 8 + gc * 2;
                *(float2*)&ep[row * EP_PITCH + col] =
                    make_float2(acc[mi][ni][0], acc[mi][ni][1]);
                *(float2*)&ep[(row + 8) * EP_PITCH + col] =
                    make_float2(acc[mi][ni][2], acc[mi][ni][3]);
            }
    }
    __syncthreads();

    {
        int lc = tid & 31;        // col group (x4)
        int rbase = tid >> 5;     // 0..7
        float4 bv = make_float4(0.f, 0.f, 0.f, 0.f);
        if (biasz) bv = *(const float4*)(biasz + n0 + lc * 4);
#pragma unroll
        for (int i = 0; i < 16; i++) {
            int row = rbase + i * 8;
            float4 v = *(float4*)&ep[row * EP_PITCH + lc * 4];
            v.x += bv.x; v.y += bv.y; v.z += bv.z; v.w += bv.w;
            ll off = coff + (ll)row * ldc + lc * 4;
            if (Cf) *(float4*)(Cf + off) = v;
            if (Chi) {
                if (Clo) {
                    // bf16 split output
                    __nv_bfloat16 h0 = __float2bfloat16(v.x);
                    __nv_bfloat16 h1 = __float2bfloat16(v.y);
                    __nv_bfloat16 h2 = __float2bfloat16(v.z);
                    __nv_bfloat16 h3 = __float2bfloat16(v.w);
                    __nv_bfloat16 l0 = __float2bfloat16(v.x - __bfloat162float(h0));
                    __nv_bfloat16 l1 = __float2bfloat16(v.y - __bfloat162float(h1));
                    __nv_bfloat16 l2 = __float2bfloat16(v.z - __bfloat162float(h2));
                    __nv_bfloat16 l3 = __float2bfloat16(v.w - __bfloat162float(h3));
                    uint2 hv, lv;
                    __nv_bfloat16* hp = (__nv_bfloat16*)&hv;
                    __nv_bfloat16* lp = (__nv_bfloat16*)&lv;
                    hp[0] = h0; hp[1] = h1; hp[2] = h2; hp[3] = h3;
                    lp[0] = l0; lp[1] = l1; lp[2] = l2; lp[3] = l3;
                    *(uint2*)(Chi + off) = hv;
                    *(uint2*)(Clo + off) = lv;
                } else {
                    // fp16 single output
                    uint2 hv;
                    __half* hp = (__half*)&hv;
                    hp[0] = __float2half(v.x);
                    hp[1] = __float2half(v.y);
                    hp[2] = __float2half(v.z);
                    hp[3] = __float2half(v.w);
                    *(uint2*)((__half*)Chi + off) = hv;
                }
            }
        }
    }
}

// ---------------------------------------------------------------------------
// Fused BN folding for all three weight sets.
// ---------------------------------------------------------------------------
__global__ void fold_all(const float* __restrict__ W_phi,
                         const float* __restrict__ pg, const float* __restrict__ pb,
                         const float* __restrict__ pm, const float* __restrict__ pv,
                         const float* __restrict__ W_psi,
                         const float* __restrict__ sg, const float* __restrict__ sb,
                         const float* __restrict__ sm, const float* __restrict__ sv,
                         const float* __restrict__ W_red,
                         const float* __restrict__ rg, const float* __restrict__ rb,
                         const float* __restrict__ rm, const float* __restrict__ rv,
                         float* __restrict__ Wphi_f, float* __restrict__ bphi,
                         float* __restrict__ Wpsi_f,
                         __half* __restrict__ Wred_f16, float* __restrict__ bred)
{
    int blk = blockIdx.x;
    int tid = threadIdx.x;
    __shared__ float red[256];
    if (blk < HP) {
        int o = blk;
        float partial = 0.f;
        const float* wrow = W_phi + (ll)o * D_;
        float* wfrow = Wphi_f + (ll)o * D_;
        for (int d = tid; d < D_; d += 256) {
            float sc = pg[d] * rsqrtf(pv[d] + 1e-5f);
            float sh = pb[d] - pm[d] * sc;
            float w = wrow[d];
            wfrow[d] = w * sc;
            partial += w * sh;
        }
        red[tid] = partial;
        __syncthreads();
        for (int s = 128; s > 0; s >>= 1) {
            if (tid < s) red[tid] += red[tid + s];
            __syncthreads();
        }
        if (tid == 0) bphi[o] = red[0];
    } else if (blk < HP + PROJ) {
        int o = blk - HP;
        const float* wrow = W_psi + (ll)o * D_;
        float* wfrow = Wpsi_f + (ll)o * D_;
        for (int d = tid; d < D_; d += 256) {
            float sc = sg[d] * rsqrtf(sv[d] + 1e-5f);
            wfrow[d] = wrow[d] * sc;
        }
    } else {
        int o = blk - HP - PROJ;
        float partial = 0.f;
        const float* wrow = W_red + (ll)o * HD;
        __half* wfr = Wred_f16 + (ll)o * HD;
        for (int d = tid; d < HD; d += 256) {
            float sc = rg[d] * rsqrtf(rv[d] + 1e-5f);
            float sh = rb[d] - rm[d] * sc;
            float w = wrow[d];
            wfr[d] = __float2half(w * sc);
            partial += w * sh;
        }
        red[tid] = partial;
        __syncthreads();
        for (int s = 128; s > 0; s >>= 1) {
            if (tid < s) red[tid] += red[tid + s];
            __syncthreads();
        }
        if (tid == 0) bred[o] = red[0];
    }
}

// ---------------------------------------------------------------------------
// Fused transpose of both folded weights: fp32 [R,C] -> split bf16 [C,R].
// ---------------------------------------------------------------------------
__global__ void __launch_bounds__(256)
transpose_both(const float* __restrict__ wphi, __nv_bfloat16* __restrict__ phi_hi,
               __nv_bfloat16* __restrict__ phi_lo,
               const float* __restrict__ wpsi, __nv_bfloat16* __restrict__ psi_hi,
               __nv_bfloat16* __restrict__ psi_lo)
{
    __shared__ float t[32][33];
    const float* in;
    __nv_bfloat16 *ohi, *olo;
    int R, r0;
    if (blockIdx.x < HP / 32) {
        in = wphi; ohi = phi_hi; olo = phi_lo; R = HP; r0 = blockIdx.x * 32;
    } else {
        in = wpsi; ohi = psi_hi; olo = psi_lo; R = PROJ;
        r0 = (blockIdx.x - HP / 32) * 32;
    }
    int c0 = blockIdx.y * 32;
#pragma unroll
    for (int j = 0; j < 4; j++) {
        int r = threadIdx.y + j * 8;
        t[r][threadIdx.x] = in[(ll)(r0 + r) * D_ + c0 + threadIdx.x];
    }
    __syncthreads();
#pragma unroll
    for (int j = 0; j < 4; j++) {
        int c = threadIdx.y + j * 8;
        float v = t[threadIdx.x][c];
        __nv_bfloat16 hi = __float2bfloat16(v);
        ll off = (ll)(c0 + c) * R + r0 + threadIdx.x;
        ohi[off] = hi;
        olo[off] = __float2bfloat16(v - __bfloat162float(hi));
    }
}

// ---------------------------------------------------------------------------
// u[g][d] = sum_p bphi[g*PROJ+p] * Wpsi_f[p][d]
// ---------------------------------------------------------------------------
__global__ void __launch_bounds__(512)
u_kernel(const float* __restrict__ bphi, const float* __restrict__ wpsi,
         float* __restrict__ u)
{
    int g = blockIdx.x;
    int d = threadIdx.x;
    float acc = 0.f;
    const float* bp = bphi + g * PROJ;
    for (int p = 0; p < PROJ; p++)
        acc += bp[p] * wpsi[(ll)p * D_ + d];
    u[g * D_ + d] = acc;
}

// ---------------------------------------------------------------------------
// cb[g][b*TK+k] = sum_d h[b][k][d] * u[g][d].  One warp per (b,k) row.
// ---------------------------------------------------------------------------
__global__ void __launch_bounds__(256)
colbias_kernel(const float* __restrict__ h, const float* __restrict__ u,
               float* __restrict__ cb)
{
    __shared__ float us[NH * D_];
    int tid = threadIdx.x;
    for (int i = tid; i < NH * D_; i += 256) us[i] = u[i];
    __syncthreads();
    int w = tid >> 5, l = tid & 31;
    ll r = (ll)blockIdx.x * 8 + w;          // (b,k) row in [0, B_*TK)
    const float* row = h + r * D_;
    float a0 = 0.f, a1 = 0.f, a2 = 0.f, a3 = 0.f;
    for (int i = l; i < D_; i += 32) {
        float v = row[i];
        a0 += v * us[i];
        a1 += v * us[D_ + i];
        a2 += v * us[2 * D_ + i];
        a3 += v * us[3 * D_ + i];
    }
#pragma unroll
    for (int s = 16; s > 0; s >>= 1) {
        a0 += __shfl_xor_sync(0xFFFFFFFF, a0, s);
        a1 += __shfl_xor_sync(0xFFFFFFFF, a1, s);
        a2 += __shfl_xor_sync(0xFFFFFFFF, a2, s);
        a3 += __shfl_xor_sync(0xFFFFFFFF, a3, s);
    }
    if (l == 0) {
        const ll BT = (ll)B_ * TK;
        cb[r] = a0;
        cb[BT + r] = a1;
        cb[2 * BT + r] = a2;
        cb[3 * BT + r] = a3;
    }
}

// ---------------------------------------------------------------------------
// Elementwise fp32 -> bf16 hi/lo split (for s); read-once input -> .cs load
// ---------------------------------------------------------------------------
__global__ void __launch_bounds__(256)
split_kernel(const float* __restrict__ x, __nv_bfloat16* __restrict__ hi,
             __nv_bfloat16* __restrict__ lo, ll n4)
{
    ll i = (ll)blockIdx.x * 256 + threadIdx.x;
    if (i >= n4) return;
    float4 v = ldg_cs4(x + i * 4);
    __nv_bfloat16 h0 = __float2bfloat16(v.x);
    __nv_bfloat16 h1 = __float2bfloat16(v.y);
    __nv_bfloat16 h2 = __float2bfloat16(v.z);
    __nv_bfloat16 h3 = __float2bfloat16(v.w);
    uint2 hv, lv;
    __nv_bfloat16* hp = (__nv_bfloat16*)&hv;
    __nv_bfloat16* lp = (__nv_bfloat16*)&lv;
    hp[0] = h0; hp[1] = h1; hp[2] = h2; hp[3] = h3;
    lp[0] = __float2bfloat16(v.x - __bfloat162float(h0));
    lp[1] = __float2bfloat16(v.y - __bfloat162float(h1));
    lp[2] = __float2bfloat16(v.z - __bfloat162float(h2));
    lp[3] = __float2bfloat16(v.w - __bfloat162float(h3));
    *(uint2*)(hi + i * 4) = hv;
    *(uint2*)(lo + i * 4) = lv;
}

// ---------------------------------------------------------------------------
// Fused h prep, vectorized: one read of h produces h_hi/h_lo (row-major,
// uint2 stores) AND ht fp16 (transposed [b][d][k], uint2 stores).
// ---------------------------------------------------------------------------
__global__ void __launch_bounds__(256)
prep_h(const float* __restrict__ h, __nv_bfloat16* __restrict__ hhi,
       __nv_bfloat16* __restrict__ hlo, __half* __restrict__ tf)
{
    __shared__ float t[32][33];
    int b = blockIdx.z;
    int k0 = blockIdx.x * 32;
    int d0 = blockIdx.y * 32;
    int tx = threadIdx.x;     // 0..7  (d quad)
    int ty = threadIdx.y;     // 0..31 (k)
    const float* hb = h + (ll)b * TK * D_;

    float4 v = *(const float4*)(hb + (ll)(k0 + ty) * D_ + d0 + tx * 4);
    t[ty][tx * 4 + 0] = v.x;
    t[ty][tx * 4 + 1] = v.y;
    t[ty][tx * 4 + 2] = v.z;
    t[ty][tx * 4 + 3] = v.w;

    {
        __nv_bfloat16 h0 = __float2bfloat16(v.x);
        __nv_bfloat16 h1 = __float2bfloat16(v.y);
        __nv_bfloat16 h2 = __float2bfloat16(v.z);
        __nv_bfloat16 h3 = __float2bfloat16(v.w);
        uint2 hv, lv;
        __nv_bfloat16* hp = (__nv_bfloat16*)&hv;
        __nv_bfloat16* lp = (__nv_bfloat16*)&lv;
        hp[0] = h0; hp[1] = h1; hp[2] = h2; hp[3] = h3;
        lp[0] = __float2bfloat16(v.x - __bfloat162float(h0));
        lp[1] = __float2bfloat16(v.y - __bfloat162float(h1));
        lp[2] = __float2bfloat16(v.z - __bfloat162float(h2));
        lp[3] = __float2bfloat16(v.w - __bfloat162float(h3));
        ll off = (ll)b * TK * D_ + (ll)(k0 + ty) * D_ + d0 + tx * 4;
        *(uint2*)(hhi + off) = hv;
        *(uint2*)(hlo + off) = lv;
    }
    __syncthreads();

    {
        float a0 = t[tx * 4 + 0][ty];
        float a1 = t[tx * 4 + 1][ty];
        float a2 = t[tx * 4 + 2][ty];
        float a3 = t[tx * 4 + 3][ty];
        __half2 p01 = __floats2half2_rn(a0, a1);
        __half2 p23 = __floats2half2_rn(a2, a3);
        uint2 hv;
        hv.x = *(uint32_t*)&p01;
        hv.y = *(uint32_t*)&p23;
        *(uint2*)(tf + (ll)b * D_ * TK + (ll)(d0 + ty) * TK + k0 + tx * 4) = hv;
    }
}

// ---------------------------------------------------------------------------
// Row softmax, in place, + fp16 copy. Warp-per-row, 8 rows per 256-thread
// block, zero block barriers, MLP=8 float4 loads per thread.
// fp32 input is dead after read, fp32 output never read again -> .cs hints,
// keeping L2 lines for a_f16 / ht_f16 that the ctx GEMM consumes next.
// ---------------------------------------------------------------------------
__global__ void __launch_bounds__(256)
softmax_kernel(float* __restrict__ a, __half* __restrict__ af16)
{
    int w = threadIdx.x >> 5, lane = threadIdx.x & 31;
    ll row = (ll)blockIdx.x * 8 + w;
    float* rp = a + row * TK;

    float4 x[8];
#pragma unroll
    for (int i = 0; i < 8; i++)
        x[i] = ldg_cs4(rp + i * 128 + lane * 4);

    float m = -INFINITY;
#pragma unroll
    for (int i = 0; i < 8; i++)
        m = fmaxf(m, fmaxf(fmaxf(x[i].x, x[i].y), fmaxf(x[i].z, x[i].w)));
#pragma unroll
    for (int s = 16; s > 0; s >>= 1)
        m = fmaxf(m, __shfl_xor_sync(0xFFFFFFFF, m, s));

    float sum = 0.f;
#pragma unroll
    for (int i = 0; i < 8; i++) {
        x[i].x = __expf(x[i].x - m);
        x[i].y = __expf(x[i].y - m);
        x[i].z = __expf(x[i].z - m);
        x[i].w = __expf(x[i].w - m);
        sum += (x[i].x + x[i].y) + (x[i].z + x[i].w);
    }
#pragma unroll
    for (int s = 16; s > 0; s >>= 1)
        sum += __shfl_xor_sync(0xFFFFFFFF, sum, s);
    float inv = 1.f / sum;

    __half* fp = af16 + row * TK;
#pragma unroll
    for (int i = 0; i < 8; i++) {
        float4 o = make_float4(x[i].x * inv, x[i].y * inv,
                               x[i].z * inv, x[i].w * inv);
        stg_cs4(rp + i * 128 + lane * 4, o);
        __half2 h01 = __floats2half2_rn(o.x, o.y);
        __half2 h23 = __floats2half2_rn(o.z, o.w);
        uint2 hv;
        hv.x = *(uint32_t*)&h01;
        hv.y = *(uint32_t*)&h23;
        *(uint2*)(fp + i * 128 + lane * 4) = hv;
    }
}

// ---------------------------------------------------------------------------
extern "C" void kernel_launch(void* const* d_in, const int* in_sizes, int n_in,
                              void* d_out, int out_size)
{
    const float* s_in      = (const float*)d_in[0];
    const float* h_in      = (const float*)d_in[1];
    const float* phi_gamma = (const float*)d_in[2];
    const float* phi_beta  = (const float*)d_in[3];
    const float* phi_mean  = (const float*)d_in[4];
    const float* phi_var   = (const float*)d_in[5];
    const float* W_phi     = (const float*)d_in[6];
    const float* psi_gamma = (const float*)d_in[7];
    const float* psi_beta  = (const float*)d_in[8];
    const float* psi_mean  = (const float*)d_in[9];
    const float* psi_var   = (const float*)d_in[10];
    const float* W_psi     = (const float*)d_in[11];
    const float* red_gamma = (const float*)d_in[12];
    const float* red_beta  = (const float*)d_in[13];
    const float* red_mean  = (const float*)d_in[14];
    const float* red_var   = (const float*)d_in[15];
    const float* W_red     = (const float*)d_in[16];

    float* a_out = (float*)d_out;               // [H, B, Tq, Tk]
    float* c_out = a_out + A_ELEMS;             // [B, Tq, D]

    __nv_bfloat16 *s_hi, *s_lo, *h_hi, *h_lo;
    __nv_bfloat16 *ms_hi, *ms_lo;
    __nv_bfloat16 *WphiT_hi, *WphiT_lo, *WpsiT_hi, *WpsiT_lo, *Gt_hi, *Gt_lo;
    __half *ht_f16, *a_f16, *ctx_f16, *Wred_f16;
    float *bphi, *bred, *Wphi_f, *Wpsi_f, *u_dev, *cb;
    cudaGetSymbolAddress((void**)&s_hi, g_s_hi);   cudaGetSymbolAddress((void**)&s_lo, g_s_lo);
    cudaGetSymbolAddress((void**)&h_hi, g_h_hi);   cudaGetSymbolAddress((void**)&h_lo, g_h_lo);
    cudaGetSymbolAddress((void**)&ht_f16, g_ht_f16);
    cudaGetSymbolAddress((void**)&ms_hi, g_ms_hi); cudaGetSymbolAddress((void**)&ms_lo, g_ms_lo);
    cudaGetSymbolAddress((void**)&a_f16, g_a_f16);
    cudaGetSymbolAddress((void**)&ctx_f16, g_ctx_f16);
    cudaGetSymbolAddress((void**)&Wred_f16, g_Wred_f16);
    cudaGetSymbolAddress((void**)&WphiT_hi, g_WphiT_hi); cudaGetSymbolAddress((void**)&WphiT_lo, g_WphiT_lo);
    cudaGetSymbolAddress((void**)&WpsiT_hi, g_WpsiT_hi); cudaGetSymbolAddress((void**)&WpsiT_lo, g_WpsiT_lo);
    cudaGetSymbolAddress((void**)&Gt_hi, g_Gt_hi); cudaGetSymbolAddress((void**)&Gt_lo, g_Gt_lo);
    cudaGetSymbolAddress((void**)&Wphi_f, g_Wphi_f); cudaGetSymbolAddress((void**)&Wpsi_f, g_Wpsi_f);
    cudaGetSymbolAddress((void**)&u_dev, g_u); cudaGetSymbolAddress((void**)&cb, g_cb);
    cudaGetSymbolAddress((void**)&bphi, g_bphi);
    cudaGetSymbolAddress((void**)&bred, g_bred);

    cudaFuncSetAttribute(gemm_tc<0>, cudaFuncAttributeMaxDynamicSharedMemorySize,
                         SMEM_MODE0);
    cudaFuncSetAttribute(gemm_tc<1>, cudaFuncAttributeMaxDynamicSharedMemorySize,
                         SMEM_MODE1);

    // ---- streams & events: prep-phase fork only (falls back to serial) ----
    cudaStream_t sA = 0;
    if (cudaStreamCreateWithFlags(&sA, cudaStreamNonBlocking) != cudaSuccess) sA = 0;
    cudaEvent_t evF, evSplit, evFold, evPrep;
    cudaEventCreateWithFlags(&evF,     cudaEventDisableTiming);
    cudaEventCreateWithFlags(&evSplit, cudaEventDisableTiming);
    cudaEventCreateWithFlags(&evFold,  cudaEventDisableTiming);
    cudaEventCreateWithFlags(&evPrep,  cudaEventDisableTiming);

    // fork
    cudaEventRecord(evF, 0);
    cudaStreamWaitEvent(sA, evF, 0);

    // ---- side stream: input conversions + bias pipeline ----
    split_kernel<<<(int)(((ll)B_ * TQ * D_ / 4 + 255) / 256), 256, 0, sA>>>(
        s_in, s_hi, s_lo, (ll)B_ * TQ * D_ / 4);
    cudaEventRecord(evSplit, sA);
    prep_h<<<dim3(TK / 32, D_ / 32, B_), dim3(8, 32), 0, sA>>>(h_in, h_hi, h_lo, ht_f16);

    // ---- main stream: weight pipeline ----
    fold_all<<<HP + PROJ + D_, 256, 0, 0>>>(
        W_phi, phi_gamma, phi_beta, phi_mean, phi_var,
        W_psi, psi_gamma, psi_beta, psi_mean, psi_var,
        W_red, red_gamma, red_beta, red_mean, red_var,
        Wphi_f, bphi, Wpsi_f, Wred_f16, bred);
    cudaEventRecord(evFold, 0);
    transpose_both<<<dim3((HP + PROJ) / 32, D_ / 32), dim3(32, 8), 0, 0>>>(
        Wphi_f, WphiT_hi, WphiT_lo, Wpsi_f, WpsiT_hi, WpsiT_lo);

    // side: u & colbias need fold_all's bphi/Wpsi_f
    cudaStreamWaitEvent(sA, evFold, 0);
    u_kernel<<<NH, 512, 0, sA>>>(bphi, Wpsi_f, u_dev);
    colbias_kernel<<<(int)((ll)B_ * TK / 8), 256, 0, sA>>>(h_in, u_dev, cb);
    cudaEventRecord(evPrep, sA);

    // main: Gt GEMM
    gemm_tc<0><<<dim3(4, 4, NH), 256, SMEM_MODE0, 0>>>(
        WpsiT_hi, WpsiT_lo, WphiT_hi, WphiT_lo, nullptr,
        nullptr, Gt_hi, Gt_lo,
        PROJ, PROJ, HP, D_,
        1, 0, 0, (ll)PROJ, 0, (ll)D_ * D_, 0, 0, 0);

    // ---- join: everything below is serial on the main stream ----
    cudaStreamWaitEvent(0, evSplit, 0);
    // 5. sG = s @ Gt^T : [8192, 2048], K=512 -> split out (ms buffers)
    gemm_tc<0><<<dim3(HP / 128, (B_ * TQ) / 128, 1), 256, SMEM_MODE0, 0>>>(
        s_hi, s_lo, Gt_hi, Gt_lo, nullptr,
        nullptr, ms_hi, ms_lo,
        D_, D_, D_, HP,
        1, 0, 0, 0, 0, 0, 0, 0, 0);

    cudaStreamWaitEvent(0, evPrep, 0);
    // 6. logits e[g,b,q,k] = sG_g[b,q,:] . h[b,k,:] + cb[g,b,k] -> fp32 a_out
    gemm_tc<0><<<dim3(TK / 128, TQ / 128, B_ * NH), 256, SMEM_MODE0, 0>>>(
        ms_hi, ms_lo, h_hi, h_lo, cb,
        a_out, nullptr, nullptr,
        D_, HP, D_, TK,
        NH,
        (ll)TQ * HP, (ll)PROJ,
        (ll)TK * D_, 0,
        (ll)TQ * TK, (ll)B_ * TQ * TK,
        (ll)TK, (ll)B_ * TK);

    // 7. softmax (in place) + fp16 copy — warp-per-row, 8 rows/block
    softmax_kernel<<<NH * B_ * TQ / 8, 256, 0, 0>>>(a_out, a_f16);

    // 8. ctx[b,q,g*D+d] = a[g,b,q,:] . ht[b,d,:]  (fp16 1-pass) -> fp16 single out
    gemm_tc<1><<<dim3(D_ / 128, TQ / 128, B_ * NH), 256, SMEM_MODE1, 0>>>(
        (const __nv_bfloat16*)a_f16, nullptr,
        (const __nv_bfloat16*)ht_f16, nullptr, nullptr,
        nullptr, (__nv_bfloat16*)ctx_f16, nullptr,
        TK, TK, TK, HD,
        NH,
        (ll)TQ * TK, (ll)B_ * TQ * TK,
        (ll)D_ * TK, 0,
        (ll)TQ * HD, (ll)D_,
        0, 0);

    // 9. c = ctx @ Wred^T + bred : [8192, 512], K=2048 (fp16 1-pass) -> fp32 out
    gemm_tc<1><<<dim3(D_ / 128, (B_ * TQ) / 128, 1), 256, SMEM_MODE1, 0>>>(
        (const __nv_bfloat16*)ctx_f16, nullptr,
        (const __nv_bfloat16*)Wred_f16, nullptr, bred,
        c_out, nullptr, nullptr,
        HD, HD, HD, D_,
        1, 0, 0, 0, 0, 0, 0, 0, 0);
    // (streams/events intentionally not destroyed; kernel_launch is called
    //  only a handful of times outside the timed graph replay)
}